// round 1
// baseline (speedup 1.0000x reference)
#include <cuda_runtime.h>
#include <math.h>

// Problem constants
constexpr int B_ = 4, S_ = 2048, E_ = 1024, H_ = 16, D_ = 64;
constexpr int M_ = B_ * S_;            // 8192 rows
constexpr int NKQV = 3 * E_;           // 3072

// Scratch (device globals: allocation-free per harness rules)
__device__ float g_k[(size_t)B_ * H_ * S_ * D_];
__device__ float g_q[(size_t)B_ * H_ * S_ * D_];
__device__ float g_v[(size_t)B_ * H_ * S_ * D_];
__device__ float g_y[(size_t)B_ * S_ * E_];

// ---------------------------------------------------------------------------
// GEMM: C[M,N] = A[M,K] @ Bw[N,K]^T + bias[N]   (both operands K-contiguous)
// BM=BN=128, BK=16, 256 threads, 8x8 microtile.
// MODE 0: plain row-major C.  MODE 1: scatter into g_k/g_q/g_v ([B,H,S,D]).
// ---------------------------------------------------------------------------
constexpr int BM = 128, BN = 128, BK = 16, TM = 8, TN = 8;
constexpr int APAD = 4;   // As stride 132: 2-way instead of 4-way STS conflicts

template <int MODE>
__global__ __launch_bounds__(256) void gemm_nt(
    const float* __restrict__ A, const float* __restrict__ Bw,
    const float* __restrict__ bias, float* __restrict__ C,
    int M, int N, int K)
{
    __shared__ float As[BK][BM + APAD];
    __shared__ float Bs[BK][BN + APAD];

    const int tid = threadIdx.x;
    const int tx = tid & 15;         // n microtile index
    const int ty = tid >> 4;         // m microtile index
    const int m0 = blockIdx.y * BM;
    const int n0 = blockIdx.x * BN;

    const float* Ap = A + (size_t)m0 * K;
    const float* Bp = Bw + (size_t)n0 * K;

    float acc[TM][TN];
#pragma unroll
    for (int i = 0; i < TM; i++)
#pragma unroll
        for (int j = 0; j < TN; j++) acc[i][j] = 0.f;

    for (int k0 = 0; k0 < K; k0 += BK) {
        // Each tile is 128 rows x 16 cols = 512 float4; 2 per thread per matrix
#pragma unroll
        for (int t = 0; t < 2; t++) {
            int idx = tid + t * 256;
            int row = idx >> 2;
            int kv  = idx & 3;
            float4 av = *(const float4*)(Ap + (size_t)row * K + k0 + kv * 4);
            As[kv * 4 + 0][row] = av.x;
            As[kv * 4 + 1][row] = av.y;
            As[kv * 4 + 2][row] = av.z;
            As[kv * 4 + 3][row] = av.w;
            float4 bv = *(const float4*)(Bp + (size_t)row * K + k0 + kv * 4);
            Bs[kv * 4 + 0][row] = bv.x;
            Bs[kv * 4 + 1][row] = bv.y;
            Bs[kv * 4 + 2][row] = bv.z;
            Bs[kv * 4 + 3][row] = bv.w;
        }
        __syncthreads();

#pragma unroll
        for (int k = 0; k < BK; k++) {
            float a[TM], b[TN];
            *(float4*)&a[0] = *(const float4*)&As[k][ty * TM];
            *(float4*)&a[4] = *(const float4*)&As[k][ty * TM + 4];
            *(float4*)&b[0] = *(const float4*)&Bs[k][tx * TN];
            *(float4*)&b[4] = *(const float4*)&Bs[k][tx * TN + 4];
#pragma unroll
            for (int i = 0; i < TM; i++)
#pragma unroll
                for (int j = 0; j < TN; j++) acc[i][j] += a[i] * b[j];
        }
        __syncthreads();
    }

    // Epilogue
#pragma unroll
    for (int i = 0; i < TM; i++) {
        const int m = m0 + ty * TM + i;
#pragma unroll
        for (int j = 0; j < TN; j++) {
            const int n = n0 + tx * TN + j;
            float v = acc[i][j] + bias[n];
            if (MODE == 0) {
                C[(size_t)m * N + n] = v;
            } else {
                // n -> which(k,q,v), head h, dim d; m -> batch b, seq s
                const int which = n >> 10;
                const int e = n & 1023;
                const int h = e >> 6;
                const int d = e & 63;
                const int b = m >> 11;        // S_ = 2048
                const int s = m & 2047;
                const size_t off = ((((size_t)b * H_ + h) * S_) + s) * D_ + d;
                if (which == 0)       g_k[off] = v;
                else if (which == 1)  g_q[off] = v;
                else                  g_v[off] = v;
            }
        }
    }
}

// ---------------------------------------------------------------------------
// Causal flash attention, fp32. One CTA per (q-tile of 64, b*h).
// 256 threads = 16x16 grid; each thread owns a 4x4 microtile.
// Shared: Qs/Ks transposed [d][{q,k}] stride 68 (padded), Vs [k][d] stride 64.
// P (post-softmax tile) reuses the Ks buffer, stored natural [q][k] stride 68.
// ---------------------------------------------------------------------------
constexpr int TSTR = 68;                       // padded stride for Qs/Ks/Ps
constexpr int SM_Q = 64 * TSTR;
constexpr int SM_K = 64 * TSTR;
constexpr int SM_V = 64 * 64;
constexpr int ATTN_SMEM_BYTES = (SM_Q + SM_K + SM_V) * 4;   // 51200

__global__ __launch_bounds__(256) void flash_attn_kernel()
{
    extern __shared__ float sm[];
    float* Qs = sm;             // [d][q], stride TSTR (scaled by 1/sqrt(D))
    float* Ks = Qs + SM_Q;      // [d][k], stride TSTR; reused as P [q][k]
    float* Vs = Ks + SM_K;      // [k][d], stride 64

    const int tid = threadIdx.x;
    const int tk = tid & 15;    // k (then d) microtile index
    const int tq = tid >> 4;    // q microtile index
    const int qt = blockIdx.x;  // q tile index (0..31)
    const int bh = blockIdx.y;  // b*H + h

    const float* Qg = g_q + ((size_t)bh * S_ + qt * 64) * D_;
    const float* Kg = g_k + (size_t)bh * S_ * D_;
    const float* Vg = g_v + (size_t)bh * S_ * D_;

    // Load Q tile transposed, fold in softmax scale (1/sqrt(64) = 0.125)
#pragma unroll
    for (int t = 0; t < 16; t++) {
        int idx = tid + t * 256;
        int q = idx >> 6, d = idx & 63;
        Qs[d * TSTR + q] = Qg[idx] * 0.125f;
    }

    float mrow[4], lrow[4], o[4][4];
#pragma unroll
    for (int i = 0; i < 4; i++) {
        mrow[i] = -1e30f;
        lrow[i] = 0.f;
#pragma unroll
        for (int j = 0; j < 4; j++) o[i][j] = 0.f;
    }

    const int nkt = qt + 1;   // causal: only tiles with k <= q
    for (int kt = 0; kt < nkt; kt++) {
        __syncthreads();   // Ks/Ps buffer free (also covers initial Q load)

        // Load K transposed (scalar scatter), V natural (float4)
#pragma unroll
        for (int t = 0; t < 16; t++) {
            int idx = tid + t * 256;
            int r = idx >> 6, d = idx & 63;
            Ks[d * TSTR + r] = Kg[(size_t)(kt * 64 + r) * 64 + d];
        }
#pragma unroll
        for (int t = 0; t < 4; t++) {
            int idx = tid + t * 256;          // 1024 float4 total
            int r = idx >> 4, dv = idx & 15;
            *(float4*)&Vs[r * 64 + dv * 4] =
                *(const float4*)(Vg + (size_t)(kt * 64 + r) * 64 + dv * 4);
        }
        __syncthreads();

        // S = (Q*scale) @ K^T : 4x4 per thread
        float s[4][4];
#pragma unroll
        for (int i = 0; i < 4; i++)
#pragma unroll
            for (int j = 0; j < 4; j++) s[i][j] = 0.f;

#pragma unroll 8
        for (int d = 0; d < 64; d++) {
            float qr[4], kr[4];
            *(float4*)qr = *(const float4*)&Qs[d * TSTR + tq * 4];
            *(float4*)kr = *(const float4*)&Ks[d * TSTR + tk * 4];
#pragma unroll
            for (int i = 0; i < 4; i++)
#pragma unroll
                for (int j = 0; j < 4; j++) s[i][j] += qr[i] * kr[j];
        }

        // Causal mask (only the diagonal tile needs it)
        if (kt == qt) {
#pragma unroll
            for (int i = 0; i < 4; i++)
#pragma unroll
                for (int j = 0; j < 4; j++)
                    if (tk * 4 + j > tq * 4 + i) s[i][j] = -1e30f;
        }

        // Online softmax update
#pragma unroll
        for (int i = 0; i < 4; i++) {
            float mt = fmaxf(fmaxf(s[i][0], s[i][1]), fmaxf(s[i][2], s[i][3]));
#pragma unroll
            for (int off = 8; off > 0; off >>= 1)
                mt = fmaxf(mt, __shfl_xor_sync(0xffffffffu, mt, off));
            float mn = fmaxf(mrow[i], mt);
            float alpha = __expf(mrow[i] - mn);
            mrow[i] = mn;
            float rs = 0.f;
#pragma unroll
            for (int j = 0; j < 4; j++) {
                s[i][j] = __expf(s[i][j] - mn);
                rs += s[i][j];
            }
#pragma unroll
            for (int off = 8; off > 0; off >>= 1)
                rs += __shfl_xor_sync(0xffffffffu, rs, off);
            lrow[i] = lrow[i] * alpha + rs;
#pragma unroll
            for (int j = 0; j < 4; j++) o[i][j] *= alpha;
        }

        __syncthreads();   // everyone done reading Ks

        // Store P natural [q][k] into the Ks buffer (float4 rows)
#pragma unroll
        for (int i = 0; i < 4; i++)
            *(float4*)&Ks[(tq * 4 + i) * TSTR + tk * 4] =
                make_float4(s[i][0], s[i][1], s[i][2], s[i][3]);
        __syncthreads();

        // O += P @ V : thread tile is (q rows tq*4.., d cols tk*4..)
#pragma unroll 8
        for (int r = 0; r < 64; r++) {
            float vr[4];
            *(float4*)vr = *(const float4*)&Vs[r * 64 + tk * 4];
#pragma unroll
            for (int i = 0; i < 4; i++) {
                float p = Ks[(tq * 4 + i) * TSTR + r];   // warp broadcast
#pragma unroll
                for (int j = 0; j < 4; j++) o[i][j] += p * vr[j];
            }
        }
    }

    // Epilogue: y[b, q, h*64 + d] = o / l   (layout ready for proj GEMM)
    const int b = bh >> 4;
    const int h = bh & 15;
#pragma unroll
    for (int i = 0; i < 4; i++) {
        const float inv = 1.0f / lrow[i];
        const int q = qt * 64 + tq * 4 + i;
        float* yp = g_y + ((size_t)b * S_ + q) * E_ + h * 64 + tk * 4;
        float4 ov = make_float4(o[i][0] * inv, o[i][1] * inv,
                                o[i][2] * inv, o[i][3] * inv);
        *(float4*)yp = ov;
    }
}

// ---------------------------------------------------------------------------
// Launch
// ---------------------------------------------------------------------------
extern "C" void kernel_launch(void* const* d_in, const int* in_sizes, int n_in,
                              void* d_out, int out_size)
{
    const float* x      = (const float*)d_in[0];
    const float* W_kqv  = (const float*)d_in[1];
    const float* b_kqv  = (const float*)d_in[2];
    const float* W_proj = (const float*)d_in[3];
    const float* b_proj = (const float*)d_in[4];
    float* out = (float*)d_out;

    // Resolve device-global scratch address for the proj GEMM input
    void* y_ptr = nullptr;
    cudaGetSymbolAddress(&y_ptr, g_y);

    dim3 blk(256);

    // 1) Fused QKV projection, scattered into [B,H,S,D] k/q/v buffers
    gemm_nt<1><<<dim3(NKQV / BN, M_ / BM), blk>>>(
        x, W_kqv, b_kqv, nullptr, M_, NKQV, E_);

    // 2) Causal flash attention -> g_y [B,S,E]
    cudaFuncSetAttribute(flash_attn_kernel,
                         cudaFuncAttributeMaxDynamicSharedMemorySize,
                         ATTN_SMEM_BYTES);
    flash_attn_kernel<<<dim3(S_ / 64, B_ * H_), blk, ATTN_SMEM_BYTES>>>();

    // 3) Output projection -> d_out
    gemm_nt<0><<<dim3(E_ / BN, M_ / BM), blk>>>(
        (const float*)y_ptr, W_proj, b_proj, out, M_, E_, E_);
}

// round 3
// speedup vs baseline: 1.3079x; 1.3079x over previous
#include <cuda_runtime.h>
#include <cuda_bf16.h>
#include <cstdint>
#include <math.h>

// Problem constants
constexpr int B_ = 4, S_ = 2048, E_ = 1024, H_ = 16, D_ = 64;
constexpr int M_ = B_ * S_;            // 8192 rows
constexpr int NKQV = 3 * E_;           // 3072

// Scratch (device globals: allocation-free per harness rules)
__device__ float g_k[(size_t)B_ * H_ * S_ * D_];
__device__ float g_q[(size_t)B_ * H_ * S_ * D_];
__device__ float g_v[(size_t)B_ * H_ * S_ * D_];
__device__ float g_y[(size_t)B_ * S_ * E_];

// ===========================================================================
// bf16 split helpers
// ===========================================================================
__device__ __forceinline__ uint32_t pack_bf16x2(float a, float b) {
    __nv_bfloat16 ha = __float2bfloat16_rn(a);
    __nv_bfloat16 hb = __float2bfloat16_rn(b);
    return (uint32_t)__bfloat16_as_ushort(ha) |
           ((uint32_t)__bfloat16_as_ushort(hb) << 16);
}
__device__ __forceinline__ float bf16_resid(float a) {
    return a - __bfloat162float(__float2bfloat16_rn(a));
}

// mma.sync m16n8k16 bf16 -> f32 (HMMA; supported on base compute_103)
__device__ __forceinline__ void mma16816(float* c, const uint32_t* a,
                                         uint32_t b0, uint32_t b1) {
    asm volatile(
        "mma.sync.aligned.m16n8k16.row.col.f32.bf16.bf16.f32 "
        "{%0,%1,%2,%3}, {%4,%5,%6,%7}, {%8,%9}, {%0,%1,%2,%3};"
        : "+f"(c[0]), "+f"(c[1]), "+f"(c[2]), "+f"(c[3])
        : "r"(a[0]), "r"(a[1]), "r"(a[2]), "r"(a[3]), "r"(b0), "r"(b1));
}

// ===========================================================================
// Tensor-core GEMM: C[M,N] = A[M,K] @ Bw[N,K]^T + bias[N]
// 128x128x32 tiles, 8 warps (warp tile 64x32), bf16 hi/lo 3-MMA split,
// double-buffered SMEM. fp32 loads are split to bf16 hi/lo during staging.
// MODE 0: row-major C.  MODE 1: scatter into g_k/g_q/g_v ([B,H,S,D]).
// ===========================================================================
constexpr int BK = 32;
constexpr int STR = 40;                  // bf16 elements per SMEM row (padded)
constexpr int TILE_E = 128 * STR;        // 5120 bf16 per operand tile
constexpr int STAGE_E = 4 * TILE_E;      // Ahi, Alo, Bhi, Blo
constexpr int GEMM_SMEM = 2 * STAGE_E * 2;   // bytes: 81920

template <int MODE>
__global__ __launch_bounds__(256) void gemm_mma(
    const float* __restrict__ A, const float* __restrict__ Bw,
    const float* __restrict__ bias, float* __restrict__ C,
    int M, int N, int K)
{
    extern __shared__ __nv_bfloat16 smb[];

    const int tid = threadIdx.x;
    const int lane = tid & 31;
    const int w = tid >> 5;
    const int wm = w & 1;                // 2 warp rows of 64
    const int wn = w >> 1;               // 4 warp cols of 32
    const int g = lane >> 2;             // groupID
    const int t = lane & 3;              // threadID_in_group
    const int m0 = blockIdx.y * 128;
    const int n0 = blockIdx.x * 128;

    const float* Ap = A + (size_t)m0 * K;
    const float* Bp = Bw + (size_t)n0 * K;

    float acc[4][4][4];
#pragma unroll
    for (int i = 0; i < 4; i++)
#pragma unroll
        for (int j = 0; j < 4; j++)
#pragma unroll
            for (int e = 0; e < 4; e++) acc[i][j][e] = 0.f;

    const int nstages = K / BK;          // 32 (K=1024) or 32 for proj too

    // ---- stage loader: ldg fp32, split, sts bf16 hi/lo -------------------
    auto load_stage = [&](int s) {
        __nv_bfloat16* st = smb + (s & 1) * STAGE_E;
        const int k0 = s * BK;
#pragma unroll
        for (int i = 0; i < 4; i++) {
            int idx = tid + i * 256;
            int r = idx >> 3, c4 = idx & 7;       // row 0..127, float4 col 0..7
            int so = r * STR + c4 * 4;
            float4 v = *(const float4*)(Ap + (size_t)r * K + k0 + c4 * 4);
            *(uint2*)(st + so) =
                make_uint2(pack_bf16x2(v.x, v.y), pack_bf16x2(v.z, v.w));
            *(uint2*)(st + TILE_E + so) = make_uint2(
                pack_bf16x2(bf16_resid(v.x), bf16_resid(v.y)),
                pack_bf16x2(bf16_resid(v.z), bf16_resid(v.w)));
            float4 u = *(const float4*)(Bp + (size_t)r * K + k0 + c4 * 4);
            *(uint2*)(st + 2 * TILE_E + so) =
                make_uint2(pack_bf16x2(u.x, u.y), pack_bf16x2(u.z, u.w));
            *(uint2*)(st + 3 * TILE_E + so) = make_uint2(
                pack_bf16x2(bf16_resid(u.x), bf16_resid(u.y)),
                pack_bf16x2(bf16_resid(u.z), bf16_resid(u.w)));
        }
    };

    load_stage(0);
    __syncthreads();

    for (int s = 0; s < nstages; s++) {
        if (s + 1 < nstages) load_stage(s + 1);

        const __nv_bfloat16* st = smb + (s & 1) * STAGE_E;
        const __nv_bfloat16* Ah = st;
        const __nv_bfloat16* Al = st + TILE_E;
        const __nv_bfloat16* Bh = st + 2 * TILE_E;
        const __nv_bfloat16* Bl = st + 3 * TILE_E;

#pragma unroll
        for (int ks = 0; ks < 2; ks++) {
            const int kb = ks * 16 + t * 2;

            uint32_t ah[4][4], al[4][4];
#pragma unroll
            for (int mt = 0; mt < 4; mt++) {
                int r = (wm * 64 + mt * 16 + g) * STR;
                ah[mt][0] = *(const uint32_t*)(Ah + r + kb);
                ah[mt][1] = *(const uint32_t*)(Ah + r + 8 * STR + kb);
                ah[mt][2] = *(const uint32_t*)(Ah + r + kb + 8);
                ah[mt][3] = *(const uint32_t*)(Ah + r + 8 * STR + kb + 8);
                al[mt][0] = *(const uint32_t*)(Al + r + kb);
                al[mt][1] = *(const uint32_t*)(Al + r + 8 * STR + kb);
                al[mt][2] = *(const uint32_t*)(Al + r + kb + 8);
                al[mt][3] = *(const uint32_t*)(Al + r + 8 * STR + kb + 8);
            }
#pragma unroll
            for (int nt = 0; nt < 4; nt++) {
                int rb = (wn * 32 + nt * 8 + g) * STR;
                uint32_t bh0 = *(const uint32_t*)(Bh + rb + kb);
                uint32_t bh1 = *(const uint32_t*)(Bh + rb + kb + 8);
                uint32_t bl0 = *(const uint32_t*)(Bl + rb + kb);
                uint32_t bl1 = *(const uint32_t*)(Bl + rb + kb + 8);
#pragma unroll
                for (int mt = 0; mt < 4; mt++) {
                    mma16816(acc[mt][nt], ah[mt], bh0, bh1);   // hi*hi
                    mma16816(acc[mt][nt], al[mt], bh0, bh1);   // lo*hi
                    mma16816(acc[mt][nt], ah[mt], bl0, bl1);   // hi*lo
                }
            }
        }
        __syncthreads();
    }

    // ---- epilogue --------------------------------------------------------
#pragma unroll
    for (int mt = 0; mt < 4; mt++) {
#pragma unroll
        for (int nt = 0; nt < 4; nt++) {
            const int m = m0 + wm * 64 + mt * 16 + g;
            const int n = n0 + wn * 32 + nt * 8 + t * 2;
            const float* c = acc[mt][nt];
            float2 bv = *(const float2*)(bias + n);
            float2 r0 = make_float2(c[0] + bv.x, c[1] + bv.y);
            float2 r1 = make_float2(c[2] + bv.x, c[3] + bv.y);
            if (MODE == 0) {
                *(float2*)(C + (size_t)m * N + n) = r0;
                *(float2*)(C + (size_t)(m + 8) * N + n) = r1;
            } else {
                const int which = n >> 10;
                const int h = (n >> 6) & 15;
                const int d = n & 63;
                float* base = (which == 0 ? g_k : which == 1 ? g_q : g_v);
                const int b0i = m >> 11, s0i = m & 2047;
                *(float2*)(base + ((((size_t)b0i * H_ + h) * S_) + s0i) * D_ + d) = r0;
                const int mb = m + 8;
                const int b1i = mb >> 11, s1i = mb & 2047;
                *(float2*)(base + ((((size_t)b1i * H_ + h) * S_) + s1i) * D_ + d) = r1;
            }
        }
    }
}

// ---------------------------------------------------------------------------
// Causal flash attention, fp32 SIMT (unchanged from R1, known-good).
// ---------------------------------------------------------------------------
constexpr int TSTR = 68;
constexpr int SM_Q = 64 * TSTR;
constexpr int SM_K = 64 * TSTR;
constexpr int SM_V = 64 * 64;
constexpr int ATTN_SMEM_BYTES = (SM_Q + SM_K + SM_V) * 4;   // 51200

__global__ __launch_bounds__(256) void flash_attn_kernel()
{
    extern __shared__ float smf[];
    float* Qs = smf;
    float* Ks = Qs + SM_Q;
    float* Vs = Ks + SM_K;

    const int tid = threadIdx.x;
    const int tk = tid & 15;
    const int tq = tid >> 4;
    const int qt = blockIdx.x;
    const int bh = blockIdx.y;

    const float* Qg = g_q + ((size_t)bh * S_ + qt * 64) * D_;
    const float* Kg = g_k + (size_t)bh * S_ * D_;
    const float* Vg = g_v + (size_t)bh * S_ * D_;

#pragma unroll
    for (int t = 0; t < 16; t++) {
        int idx = tid + t * 256;
        int q = idx >> 6, d = idx & 63;
        Qs[d * TSTR + q] = Qg[idx] * 0.125f;
    }

    float mrow[4], lrow[4], o[4][4];
#pragma unroll
    for (int i = 0; i < 4; i++) {
        mrow[i] = -1e30f;
        lrow[i] = 0.f;
#pragma unroll
        for (int j = 0; j < 4; j++) o[i][j] = 0.f;
    }

    const int nkt = qt + 1;
    for (int kt = 0; kt < nkt; kt++) {
        __syncthreads();

#pragma unroll
        for (int t = 0; t < 16; t++) {
            int idx = tid + t * 256;
            int r = idx >> 6, d = idx & 63;
            Ks[d * TSTR + r] = Kg[(size_t)(kt * 64 + r) * 64 + d];
        }
#pragma unroll
        for (int t = 0; t < 4; t++) {
            int idx = tid + t * 256;
            int r = idx >> 4, dv = idx & 15;
            *(float4*)&Vs[r * 64 + dv * 4] =
                *(const float4*)(Vg + (size_t)(kt * 64 + r) * 64 + dv * 4);
        }
        __syncthreads();

        float s[4][4];
#pragma unroll
        for (int i = 0; i < 4; i++)
#pragma unroll
            for (int j = 0; j < 4; j++) s[i][j] = 0.f;

#pragma unroll 8
        for (int d = 0; d < 64; d++) {
            float qr[4], kr[4];
            *(float4*)qr = *(const float4*)&Qs[d * TSTR + tq * 4];
            *(float4*)kr = *(const float4*)&Ks[d * TSTR + tk * 4];
#pragma unroll
            for (int i = 0; i < 4; i++)
#pragma unroll
                for (int j = 0; j < 4; j++) s[i][j] += qr[i] * kr[j];
        }

        if (kt == qt) {
#pragma unroll
            for (int i = 0; i < 4; i++)
#pragma unroll
                for (int j = 0; j < 4; j++)
                    if (tk * 4 + j > tq * 4 + i) s[i][j] = -1e30f;
        }

#pragma unroll
        for (int i = 0; i < 4; i++) {
            float mt = fmaxf(fmaxf(s[i][0], s[i][1]), fmaxf(s[i][2], s[i][3]));
#pragma unroll
            for (int off = 8; off > 0; off >>= 1)
                mt = fmaxf(mt, __shfl_xor_sync(0xffffffffu, mt, off));
            float mn = fmaxf(mrow[i], mt);
            float alpha = __expf(mrow[i] - mn);
            mrow[i] = mn;
            float rs = 0.f;
#pragma unroll
            for (int j = 0; j < 4; j++) {
                s[i][j] = __expf(s[i][j] - mn);
                rs += s[i][j];
            }
#pragma unroll
            for (int off = 8; off > 0; off >>= 1)
                rs += __shfl_xor_sync(0xffffffffu, rs, off);
            lrow[i] = lrow[i] * alpha + rs;
#pragma unroll
            for (int j = 0; j < 4; j++) o[i][j] *= alpha;
        }

        __syncthreads();

#pragma unroll
        for (int i = 0; i < 4; i++)
            *(float4*)&Ks[(tq * 4 + i) * TSTR + tk * 4] =
                make_float4(s[i][0], s[i][1], s[i][2], s[i][3]);
        __syncthreads();

#pragma unroll 8
        for (int r = 0; r < 64; r++) {
            float vr[4];
            *(float4*)vr = *(const float4*)&Vs[r * 64 + tk * 4];
#pragma unroll
            for (int i = 0; i < 4; i++) {
                float p = Ks[(tq * 4 + i) * TSTR + r];
#pragma unroll
                for (int j = 0; j < 4; j++) o[i][j] += p * vr[j];
            }
        }
    }

    const int b = bh >> 4;
    const int h = bh & 15;
#pragma unroll
    for (int i = 0; i < 4; i++) {
        const float inv = 1.0f / lrow[i];
        const int q = qt * 64 + tq * 4 + i;
        float* yp = g_y + ((size_t)b * S_ + q) * E_ + h * 64 + tk * 4;
        *(float4*)yp = make_float4(o[i][0] * inv, o[i][1] * inv,
                                   o[i][2] * inv, o[i][3] * inv);
    }
}

// ---------------------------------------------------------------------------
// Launch
// ---------------------------------------------------------------------------
extern "C" void kernel_launch(void* const* d_in, const int* in_sizes, int n_in,
                              void* d_out, int out_size)
{
    const float* x      = (const float*)d_in[0];
    const float* W_kqv  = (const float*)d_in[1];
    const float* b_kqv  = (const float*)d_in[2];
    const float* W_proj = (const float*)d_in[3];
    const float* b_proj = (const float*)d_in[4];
    float* out = (float*)d_out;

    void* y_ptr = nullptr;
    cudaGetSymbolAddress(&y_ptr, g_y);

    cudaFuncSetAttribute(gemm_mma<0>, cudaFuncAttributeMaxDynamicSharedMemorySize,
                         GEMM_SMEM);
    cudaFuncSetAttribute(gemm_mma<1>, cudaFuncAttributeMaxDynamicSharedMemorySize,
                         GEMM_SMEM);
    cudaFuncSetAttribute(flash_attn_kernel,
                         cudaFuncAttributeMaxDynamicSharedMemorySize,
                         ATTN_SMEM_BYTES);

    dim3 blk(256);

    // 1) Fused QKV projection (HMMA, bf16 3-split) -> g_k/g_q/g_v
    gemm_mma<1><<<dim3(NKQV / 128, M_ / 128), blk, GEMM_SMEM>>>(
        x, W_kqv, b_kqv, nullptr, M_, NKQV, E_);

    // 2) Causal flash attention -> g_y [B,S,E]
    flash_attn_kernel<<<dim3(S_ / 64, B_ * H_), blk, ATTN_SMEM_BYTES>>>();

    // 3) Output projection (HMMA) -> d_out
    gemm_mma<0><<<dim3(E_ / 128, M_ / 128), blk, GEMM_SMEM>>>(
        (const float*)y_ptr, W_proj, b_proj, out, M_, E_, E_);
}

// round 4
// speedup vs baseline: 2.1884x; 1.6733x over previous
#include <cuda_runtime.h>
#include <cuda_bf16.h>
#include <cstdint>
#include <math.h>

// Problem constants
constexpr int B_ = 4, S_ = 2048, E_ = 1024, H_ = 16, D_ = 64;
constexpr int M_ = B_ * S_;            // 8192 rows
constexpr int NKQV = 3 * E_;           // 3072

// ---------------------------------------------------------------------------
// Scratch (device globals; bf16 hi/lo pairs)
// ---------------------------------------------------------------------------
__device__ __nv_bfloat16 g_xh[(size_t)M_ * E_],  g_xl[(size_t)M_ * E_];
__device__ __nv_bfloat16 g_wkh[(size_t)NKQV * E_], g_wkl[(size_t)NKQV * E_];
__device__ __nv_bfloat16 g_wph[(size_t)E_ * E_], g_wpl[(size_t)E_ * E_];
__device__ __nv_bfloat16 g_qh[(size_t)B_*H_*S_*D_], g_ql[(size_t)B_*H_*S_*D_];
__device__ __nv_bfloat16 g_kh[(size_t)B_*H_*S_*D_], g_kl[(size_t)B_*H_*S_*D_];
__device__ __nv_bfloat16 g_vh[(size_t)B_*H_*S_*D_], g_vl[(size_t)B_*H_*S_*D_];
__device__ __nv_bfloat16 g_vth[(size_t)B_*H_*S_*D_], g_vtl[(size_t)B_*H_*S_*D_];
__device__ __nv_bfloat16 g_yh[(size_t)M_ * E_],  g_yl[(size_t)M_ * E_];

// ---------------------------------------------------------------------------
// helpers
// ---------------------------------------------------------------------------
__device__ __forceinline__ uint32_t pack_bf16x2(float a, float b) {
    __nv_bfloat16 ha = __float2bfloat16_rn(a);
    __nv_bfloat16 hb = __float2bfloat16_rn(b);
    return (uint32_t)__bfloat16_as_ushort(ha) |
           ((uint32_t)__bfloat16_as_ushort(hb) << 16);
}
__device__ __forceinline__ float bf16_resid(float a) {
    return a - __bfloat162float(__float2bfloat16_rn(a));
}

__device__ __forceinline__ void mma16816(float* c, const uint32_t* a,
                                         uint32_t b0, uint32_t b1) {
    asm volatile(
        "mma.sync.aligned.m16n8k16.row.col.f32.bf16.bf16.f32 "
        "{%0,%1,%2,%3}, {%4,%5,%6,%7}, {%8,%9}, {%0,%1,%2,%3};"
        : "+f"(c[0]), "+f"(c[1]), "+f"(c[2]), "+f"(c[3])
        : "r"(a[0]), "r"(a[1]), "r"(a[2]), "r"(a[3]), "r"(b0), "r"(b1));
}

__device__ __forceinline__ uint32_t smem_u32(const void* p) {
    uint32_t a;
    asm("{ .reg .u64 t; cvta.to.shared.u64 t, %1; cvt.u32.u64 %0, t; }"
        : "=r"(a) : "l"(p));
    return a;
}
__device__ __forceinline__ void cp16(uint32_t dst, const void* src) {
    asm volatile("cp.async.ca.shared.global [%0], [%1], 16;"
                 :: "r"(dst), "l"(src));
}
#define CP_COMMIT() asm volatile("cp.async.commit_group;" ::: "memory")
#define CP_WAIT1()  asm volatile("cp.async.wait_group 1;" ::: "memory")
#define CP_WAIT0()  asm volatile("cp.async.wait_group 0;" ::: "memory")

// FMA-pipe exp2 (input in log2 units, x <= ~0). ~2e-6 rel err.
__device__ __forceinline__ float exp2p(float x) {
    x = fmaxf(x, -80.f);
    float t = x + 12582912.f;               // round-to-nearest-int magic
    int n = __float_as_int(t) - 0x4B400000;
    float r = x - (t - 12582912.f);         // r in [-0.5, 0.5]
    float p = 1.33335581e-3f;
    p = fmaf(p, r, 9.61812911e-3f);
    p = fmaf(p, r, 5.55041087e-2f);
    p = fmaf(p, r, 2.40226507e-1f);
    p = fmaf(p, r, 6.93147180e-1f);
    p = fmaf(p, r, 1.0f);
    return p * __int_as_float((n + 127) << 23);
}

// fold softmax scale + log2e into q at write time
constexpr float QSCALE = 0.125f * 1.44269504088896340736f;

// ---------------------------------------------------------------------------
// split: fp32 -> bf16 hi + lo
// ---------------------------------------------------------------------------
__global__ void split_kernel(const float* __restrict__ src,
                             __nv_bfloat16* __restrict__ hi,
                             __nv_bfloat16* __restrict__ lo, int n4) {
    int i = blockIdx.x * blockDim.x + threadIdx.x;
    if (i >= n4) return;
    float4 v = ((const float4*)src)[i];
    ((uint2*)hi)[i] = make_uint2(pack_bf16x2(v.x, v.y), pack_bf16x2(v.z, v.w));
    ((uint2*)lo)[i] = make_uint2(
        pack_bf16x2(bf16_resid(v.x), bf16_resid(v.y)),
        pack_bf16x2(bf16_resid(v.z), bf16_resid(v.w)));
}

// ---------------------------------------------------------------------------
// GEMM: C[M,N] = (Ah+Al)[M,K] @ (Bh+Bl)[N,K]^T + bias
// 128x128x32 tiles, 8 warps, 3-stage cp.async pipeline, 3-MMA hi/lo split.
// MODE 0: fp32 row-major C.  MODE 1: bf16 hi/lo scatter to q/k/v buffers.
// ---------------------------------------------------------------------------
constexpr int GBK = 32;
constexpr int GSTR = 40;                     // padded bf16 stride
constexpr int GTILE_E = 128 * GSTR;          // 5120
constexpr int GSTAGE_E = 4 * GTILE_E;        // 20480
constexpr int GSMEM = 3 * GSTAGE_E * 2;      // 122880 B

template <int MODE>
__global__ __launch_bounds__(256) void gemm_cp(
    const __nv_bfloat16* __restrict__ Ah, const __nv_bfloat16* __restrict__ Al,
    const __nv_bfloat16* __restrict__ Bh, const __nv_bfloat16* __restrict__ Bl,
    const float* __restrict__ bias, float* __restrict__ C,
    int M, int N, int K)
{
    extern __shared__ __nv_bfloat16 smb[];
    const int tid = threadIdx.x;
    const int lane = tid & 31;
    const int w = tid >> 5;
    const int wm = w & 1, wn = w >> 1;
    const int g = lane >> 2, t = lane & 3;
    const int m0 = blockIdx.y * 128;
    const int n0 = blockIdx.x * 128;

    const __nv_bfloat16* bases[4] = {
        Ah + (size_t)m0 * K, Al + (size_t)m0 * K,
        Bh + (size_t)n0 * K, Bl + (size_t)n0 * K };

    const int nsteps = K / GBK;

    auto issue = [&](int s) {
        __nv_bfloat16* st = smb + (s % 3) * GSTAGE_E;
        const int k0 = s * GBK;
#pragma unroll
        for (int c = 0; c < 8; c++) {
            int ci = tid + c * 256;
            int arr = ci >> 9;
            int idx = ci & 511;
            int r = idx >> 2, ch = idx & 3;
            const __nv_bfloat16* src = bases[arr] + (size_t)r * K + k0 + ch * 8;
            cp16(smem_u32(st + arr * GTILE_E + r * GSTR + ch * 8), src);
        }
        CP_COMMIT();
    };

    float acc[4][4][4];
#pragma unroll
    for (int i = 0; i < 4; i++)
#pragma unroll
        for (int j = 0; j < 4; j++)
#pragma unroll
            for (int e = 0; e < 4; e++) acc[i][j][e] = 0.f;

    issue(0);
    issue(1);

    for (int s = 0; s < nsteps; s++) {
        if (s + 1 < nsteps) { CP_WAIT1(); } else { CP_WAIT0(); }
        __syncthreads();
        if (s + 2 < nsteps) issue(s + 2);

        const __nv_bfloat16* st = smb + (s % 3) * GSTAGE_E;
        const __nv_bfloat16* Ah_ = st;
        const __nv_bfloat16* Al_ = st + GTILE_E;
        const __nv_bfloat16* Bh_ = st + 2 * GTILE_E;
        const __nv_bfloat16* Bl_ = st + 3 * GTILE_E;

#pragma unroll
        for (int ks = 0; ks < 2; ks++) {
            const int kb = ks * 16 + t * 2;
            uint32_t ah[4][4], al[4][4];
#pragma unroll
            for (int mt = 0; mt < 4; mt++) {
                int r = (wm * 64 + mt * 16 + g) * GSTR;
                ah[mt][0] = *(const uint32_t*)(Ah_ + r + kb);
                ah[mt][1] = *(const uint32_t*)(Ah_ + r + 8 * GSTR + kb);
                ah[mt][2] = *(const uint32_t*)(Ah_ + r + kb + 8);
                ah[mt][3] = *(const uint32_t*)(Ah_ + r + 8 * GSTR + kb + 8);
                al[mt][0] = *(const uint32_t*)(Al_ + r + kb);
                al[mt][1] = *(const uint32_t*)(Al_ + r + 8 * GSTR + kb);
                al[mt][2] = *(const uint32_t*)(Al_ + r + kb + 8);
                al[mt][3] = *(const uint32_t*)(Al_ + r + 8 * GSTR + kb + 8);
            }
#pragma unroll
            for (int nt = 0; nt < 4; nt++) {
                int rb = (wn * 32 + nt * 8 + g) * GSTR;
                uint32_t bh0 = *(const uint32_t*)(Bh_ + rb + kb);
                uint32_t bh1 = *(const uint32_t*)(Bh_ + rb + kb + 8);
                uint32_t bl0 = *(const uint32_t*)(Bl_ + rb + kb);
                uint32_t bl1 = *(const uint32_t*)(Bl_ + rb + kb + 8);
#pragma unroll
                for (int mt = 0; mt < 4; mt++) {
                    mma16816(acc[mt][nt], ah[mt], bh0, bh1);
                    mma16816(acc[mt][nt], al[mt], bh0, bh1);
                    mma16816(acc[mt][nt], ah[mt], bl0, bl1);
                }
            }
        }
        __syncthreads();
    }

    // ---- epilogue --------------------------------------------------------
#pragma unroll
    for (int mt = 0; mt < 4; mt++) {
#pragma unroll
        for (int nt = 0; nt < 4; nt++) {
            const int m = m0 + wm * 64 + mt * 16 + g;
            const int n = n0 + wn * 32 + nt * 8 + t * 2;
            const float* c = acc[mt][nt];
            float2 bv = *(const float2*)(bias + n);
            if (MODE == 0) {
                *(float2*)(C + (size_t)m * N + n) =
                    make_float2(c[0] + bv.x, c[1] + bv.y);
                *(float2*)(C + (size_t)(m + 8) * N + n) =
                    make_float2(c[2] + bv.x, c[3] + bv.y);
            } else {
                const int which = n >> 10;
                const int h = (n >> 6) & 15;
                const int d = n & 63;
                const float sc = (which == 1) ? QSCALE : 1.0f;
                __nv_bfloat16* dh = (which == 0 ? g_kh : which == 1 ? g_qh : g_vh);
                __nv_bfloat16* dl = (which == 0 ? g_kl : which == 1 ? g_ql : g_vl);
#pragma unroll
                for (int rr = 0; rr < 2; rr++) {
                    const int mm = m + rr * 8;
                    const int b = mm >> 11, s = mm & 2047;
                    const size_t off =
                        ((((size_t)b * H_ + h) * S_) + s) * D_ + d;
                    float v0 = (c[rr * 2 + 0] + bv.x) * sc;
                    float v1 = (c[rr * 2 + 1] + bv.y) * sc;
                    *(uint32_t*)(dh + off) = pack_bf16x2(v0, v1);
                    *(uint32_t*)(dl + off) =
                        pack_bf16x2(bf16_resid(v0), bf16_resid(v1));
                }
            }
        }
    }
}

// ---------------------------------------------------------------------------
// V transpose: [bh][s][d] -> [bh][d][s], hi and lo
// ---------------------------------------------------------------------------
__global__ __launch_bounds__(256) void vtrans_kernel() {
    __shared__ __nv_bfloat16 tile[64][72];
    const int tid = threadIdx.x;
    const int st = blockIdx.x;     // s-tile (64)
    const int bh = blockIdx.y;

    const __nv_bfloat16* srcs[2] = {
        g_vh + ((size_t)bh * S_ + st * 64) * D_,
        g_vl + ((size_t)bh * S_ + st * 64) * D_ };
    __nv_bfloat16* dsts[2] = {
        g_vth + (size_t)bh * D_ * S_ + st * 64,
        g_vtl + (size_t)bh * D_ * S_ + st * 64 };

    for (int a = 0; a < 2; a++) {
        __syncthreads();
#pragma unroll
        for (int c = 0; c < 8; c++) {
            int ci = tid + c * 256;           // u32 index: 2048
            int r = ci >> 5, ch = ci & 31;
            *(uint32_t*)&tile[r][ch * 2] =
                *(const uint32_t*)(srcs[a] + (size_t)r * D_ + ch * 2);
        }
        __syncthreads();
#pragma unroll
        for (int c = 0; c < 8; c++) {
            int ci = tid + c * 256;
            int d = ci >> 5, s2 = (ci & 31) * 2;
            uint32_t o = (uint32_t)__bfloat16_as_ushort(tile[s2][d]) |
                         ((uint32_t)__bfloat16_as_ushort(tile[s2 + 1][d]) << 16);
            *(uint32_t*)(dsts[a] + (size_t)d * S_ + s2) = o;
        }
    }
}

// ---------------------------------------------------------------------------
// Tensor-core causal flash attention.
// CTA = (q-tile 128, bh). 8 warps; warp w owns q rows w*16..w*16+15.
// K-tiles of 64; 2-buffer cp.async; 3-MMA hi/lo splits for QK^T and PV.
// exp2 in FMA pipe (scores pre-scaled by 0.125*log2e at q write).
// ---------------------------------------------------------------------------
constexpr int ASTR = 72;
constexpr int AQ_E = 2 * 128 * ASTR;            // q hi+lo staging
constexpr int AKT_E = 64 * ASTR;                // one 64x64 operand tile
constexpr int AKSTAGE_E = 4 * AKT_E;            // kh,kl,vth,vtl
constexpr int ASMEM = (AQ_E + 2 * AKSTAGE_E) * 2;   // 110592 B

__global__ __launch_bounds__(256) void attn_mma() {
    extern __shared__ __nv_bfloat16 sma[];
    const int tid = threadIdx.x;
    const int lane = tid & 31;
    const int w = tid >> 5;
    const int g = lane >> 2, t = lane & 3;
    const int qt = (S_ / 128 - 1) - blockIdx.x;   // big tiles first
    const int bh = blockIdx.y;
    const int nkt = 2 * qt + 2;

    __nv_bfloat16* QH = sma;
    __nv_bfloat16* QL = sma + 128 * ASTR;
    __nv_bfloat16* KV0 = sma + AQ_E;

    // ---- stage Q (group 0)
    {
        const __nv_bfloat16* qsrc[2] = {
            g_qh + ((size_t)bh * S_ + qt * 128) * D_,
            g_ql + ((size_t)bh * S_ + qt * 128) * D_ };
#pragma unroll
        for (int c = 0; c < 8; c++) {
            int ci = tid + c * 256;
            int arr = ci >> 10;
            int idx = ci & 1023;
            int r = idx >> 3, ch = idx & 7;
            cp16(smem_u32(sma + arr * (128 * ASTR) + r * ASTR + ch * 8),
                 qsrc[arr] + (size_t)r * D_ + ch * 8);
        }
        CP_COMMIT();
    }

    auto issueKV = [&](int kt) {
        __nv_bfloat16* st = KV0 + (kt & 1) * AKSTAGE_E;
        const __nv_bfloat16* bases[4] = {
            g_kh + ((size_t)bh * S_ + kt * 64) * D_,
            g_kl + ((size_t)bh * S_ + kt * 64) * D_,
            g_vth + (size_t)bh * D_ * S_ + kt * 64,
            g_vtl + (size_t)bh * D_ * S_ + kt * 64 };
#pragma unroll
        for (int c = 0; c < 8; c++) {
            int ci = tid + c * 256;
            int arr = ci >> 9;
            int idx = ci & 511;
            int r = idx >> 3, ch = idx & 7;
            const size_t rs = (arr < 2) ? (size_t)D_ : (size_t)S_;
            cp16(smem_u32(st + arr * AKT_E + r * ASTR + ch * 8),
                 bases[arr] + (size_t)r * rs + ch * 8);
        }
        CP_COMMIT();
    };

    issueKV(0);
    CP_WAIT1();            // Q done (stage 0 may still be in flight)
    __syncthreads();

    // ---- Q fragments (kept in registers for the whole CTA)
    uint32_t qfh[4][4], qfl[4][4];
#pragma unroll
    for (int ks = 0; ks < 4; ks++) {
        const int kb = ks * 16 + t * 2;
        const int r0 = (w * 16 + g) * ASTR;
        qfh[ks][0] = *(const uint32_t*)(QH + r0 + kb);
        qfh[ks][1] = *(const uint32_t*)(QH + r0 + 8 * ASTR + kb);
        qfh[ks][2] = *(const uint32_t*)(QH + r0 + kb + 8);
        qfh[ks][3] = *(const uint32_t*)(QH + r0 + 8 * ASTR + kb + 8);
        qfl[ks][0] = *(const uint32_t*)(QL + r0 + kb);
        qfl[ks][1] = *(const uint32_t*)(QL + r0 + 8 * ASTR + kb);
        qfl[ks][2] = *(const uint32_t*)(QL + r0 + kb + 8);
        qfl[ks][3] = *(const uint32_t*)(QL + r0 + 8 * ASTR + kb + 8);
    }

    if (nkt > 1) issueKV(1);

    float o[8][4];
#pragma unroll
    for (int nt = 0; nt < 8; nt++)
#pragma unroll
        for (int e = 0; e < 4; e++) o[nt][e] = 0.f;
    float m0 = -1e30f, m1 = -1e30f, l0 = 0.f, l1 = 0.f;

    const int row0 = qt * 128 + w * 16 + g;
    const int row1 = row0 + 8;

    for (int kt = 0; kt < nkt; kt++) {
        if (kt + 1 < nkt) { CP_WAIT1(); } else { CP_WAIT0(); }
        __syncthreads();

        const __nv_bfloat16* st = KV0 + (kt & 1) * AKSTAGE_E;
        const __nv_bfloat16* KHs = st;
        const __nv_bfloat16* KLs = st + AKT_E;
        const __nv_bfloat16* VHs = st + 2 * AKT_E;
        const __nv_bfloat16* VLs = st + 3 * AKT_E;

        // ---- S = Q @ K^T (3-split)
        float sc[8][4];
#pragma unroll
        for (int nt = 0; nt < 8; nt++)
#pragma unroll
            for (int e = 0; e < 4; e++) sc[nt][e] = 0.f;

#pragma unroll
        for (int nt = 0; nt < 8; nt++) {
            const int rb = (nt * 8 + g) * ASTR;
#pragma unroll
            for (int ks = 0; ks < 4; ks++) {
                const int kb = ks * 16 + t * 2;
                uint32_t bh0 = *(const uint32_t*)(KHs + rb + kb);
                uint32_t bh1 = *(const uint32_t*)(KHs + rb + kb + 8);
                uint32_t bl0 = *(const uint32_t*)(KLs + rb + kb);
                uint32_t bl1 = *(const uint32_t*)(KLs + rb + kb + 8);
                mma16816(sc[nt], qfh[ks], bh0, bh1);
                mma16816(sc[nt], qfl[ks], bh0, bh1);
                mma16816(sc[nt], qfh[ks], bl0, bl1);
            }
        }

        // ---- causal mask (only last two k-tiles can cross the diagonal)
        if (kt >= 2 * qt) {
#pragma unroll
            for (int nt = 0; nt < 8; nt++) {
                const int c0 = kt * 64 + nt * 8 + 2 * t;
                if (c0 > row0)     sc[nt][0] = -1e30f;
                if (c0 + 1 > row0) sc[nt][1] = -1e30f;
                if (c0 > row1)     sc[nt][2] = -1e30f;
                if (c0 + 1 > row1) sc[nt][3] = -1e30f;
            }
        }

        // ---- online softmax (base-2; FMA-pipe exp)
        float mx0 = -1e30f, mx1 = -1e30f;
#pragma unroll
        for (int nt = 0; nt < 8; nt++) {
            mx0 = fmaxf(mx0, fmaxf(sc[nt][0], sc[nt][1]));
            mx1 = fmaxf(mx1, fmaxf(sc[nt][2], sc[nt][3]));
        }
        mx0 = fmaxf(mx0, __shfl_xor_sync(0xffffffffu, mx0, 1));
        mx0 = fmaxf(mx0, __shfl_xor_sync(0xffffffffu, mx0, 2));
        mx1 = fmaxf(mx1, __shfl_xor_sync(0xffffffffu, mx1, 1));
        mx1 = fmaxf(mx1, __shfl_xor_sync(0xffffffffu, mx1, 2));

        const float mn0 = fmaxf(m0, mx0), mn1 = fmaxf(m1, mx1);
        const float a0 = exp2p(m0 - mn0), a1 = exp2p(m1 - mn1);
        m0 = mn0; m1 = mn1;

        float rs0 = 0.f, rs1 = 0.f;
#pragma unroll
        for (int nt = 0; nt < 8; nt++) {
            sc[nt][0] = exp2p(sc[nt][0] - mn0);
            sc[nt][1] = exp2p(sc[nt][1] - mn0);
            sc[nt][2] = exp2p(sc[nt][2] - mn1);
            sc[nt][3] = exp2p(sc[nt][3] - mn1);
            rs0 += sc[nt][0] + sc[nt][1];
            rs1 += sc[nt][2] + sc[nt][3];
        }
        rs0 += __shfl_xor_sync(0xffffffffu, rs0, 1);
        rs0 += __shfl_xor_sync(0xffffffffu, rs0, 2);
        rs1 += __shfl_xor_sync(0xffffffffu, rs1, 1);
        rs1 += __shfl_xor_sync(0xffffffffu, rs1, 2);
        l0 = l0 * a0 + rs0;
        l1 = l1 * a1 + rs1;

#pragma unroll
        for (int nt = 0; nt < 8; nt++) {
            o[nt][0] *= a0; o[nt][1] *= a0;
            o[nt][2] *= a1; o[nt][3] *= a1;
        }

        // ---- P fragments from accumulators (FA layout trick) + hi/lo split
        uint32_t pfh[4][4], pfl[4][4];
#pragma unroll
        for (int ks = 0; ks < 4; ks++) {
            const float* p0 = sc[2 * ks];
            const float* p1 = sc[2 * ks + 1];
            pfh[ks][0] = pack_bf16x2(p0[0], p0[1]);
            pfh[ks][1] = pack_bf16x2(p0[2], p0[3]);
            pfh[ks][2] = pack_bf16x2(p1[0], p1[1]);
            pfh[ks][3] = pack_bf16x2(p1[2], p1[3]);
            pfl[ks][0] = pack_bf16x2(bf16_resid(p0[0]), bf16_resid(p0[1]));
            pfl[ks][1] = pack_bf16x2(bf16_resid(p0[2]), bf16_resid(p0[3]));
            pfl[ks][2] = pack_bf16x2(bf16_resid(p1[0]), bf16_resid(p1[1]));
            pfl[ks][3] = pack_bf16x2(bf16_resid(p1[2]), bf16_resid(p1[3]));
        }

        // ---- O += P @ V (3-split; V^T staged [d][s])
#pragma unroll
        for (int nt = 0; nt < 8; nt++) {
            const int rb = (nt * 8 + g) * ASTR;
#pragma unroll
            for (int ks = 0; ks < 4; ks++) {
                const int kb = ks * 16 + t * 2;
                uint32_t vh0 = *(const uint32_t*)(VHs + rb + kb);
                uint32_t vh1 = *(const uint32_t*)(VHs + rb + kb + 8);
                uint32_t vl0 = *(const uint32_t*)(VLs + rb + kb);
                uint32_t vl1 = *(const uint32_t*)(VLs + rb + kb + 8);
                mma16816(o[nt], pfh[ks], vh0, vh1);
                mma16816(o[nt], pfl[ks], vh0, vh1);
                mma16816(o[nt], pfh[ks], vl0, vl1);
            }
        }

        __syncthreads();
        if (kt + 2 < nkt) issueKV(kt + 2);
    }

    // ---- epilogue: y = O / l, bf16 hi/lo, layout [b][s][h*64+d]
    const float inv0 = 1.0f / l0, inv1 = 1.0f / l1;
    const int b = bh >> 4, h = bh & 15;
#pragma unroll
    for (int nt = 0; nt < 8; nt++) {
        const int e = h * 64 + nt * 8 + 2 * t;
        {
            const size_t off = ((size_t)b * S_ + row0) * E_ + e;
            float v0 = o[nt][0] * inv0, v1 = o[nt][1] * inv0;
            *(uint32_t*)(g_yh + off) = pack_bf16x2(v0, v1);
            *(uint32_t*)(g_yl + off) =
                pack_bf16x2(bf16_resid(v0), bf16_resid(v1));
        }
        {
            const size_t off = ((size_t)b * S_ + row1) * E_ + e;
            float v0 = o[nt][2] * inv1, v1 = o[nt][3] * inv1;
            *(uint32_t*)(g_yh + off) = pack_bf16x2(v0, v1);
            *(uint32_t*)(g_yl + off) =
                pack_bf16x2(bf16_resid(v0), bf16_resid(v1));
        }
    }
}

// ---------------------------------------------------------------------------
// Launch
// ---------------------------------------------------------------------------
extern "C" void kernel_launch(void* const* d_in, const int* in_sizes, int n_in,
                              void* d_out, int out_size)
{
    const float* x      = (const float*)d_in[0];
    const float* W_kqv  = (const float*)d_in[1];
    const float* b_kqv  = (const float*)d_in[2];
    const float* W_proj = (const float*)d_in[3];
    const float* b_proj = (const float*)d_in[4];
    float* out = (float*)d_out;

    void *xh, *xl, *wkh, *wkl, *wph, *wpl, *yh, *yl;
    cudaGetSymbolAddress(&xh, g_xh);   cudaGetSymbolAddress(&xl, g_xl);
    cudaGetSymbolAddress(&wkh, g_wkh); cudaGetSymbolAddress(&wkl, g_wkl);
    cudaGetSymbolAddress(&wph, g_wph); cudaGetSymbolAddress(&wpl, g_wpl);
    cudaGetSymbolAddress(&yh, g_yh);   cudaGetSymbolAddress(&yl, g_yl);

    cudaFuncSetAttribute(gemm_cp<0>, cudaFuncAttributeMaxDynamicSharedMemorySize, GSMEM);
    cudaFuncSetAttribute(gemm_cp<1>, cudaFuncAttributeMaxDynamicSharedMemorySize, GSMEM);
    cudaFuncSetAttribute(attn_mma,   cudaFuncAttributeMaxDynamicSharedMemorySize, ASMEM);

    // 0) split inputs to bf16 hi/lo
    {
        int n4 = M_ * E_ / 4;
        split_kernel<<<(n4 + 255) / 256, 256>>>(
            x, (__nv_bfloat16*)xh, (__nv_bfloat16*)xl, n4);
        n4 = NKQV * E_ / 4;
        split_kernel<<<(n4 + 255) / 256, 256>>>(
            W_kqv, (__nv_bfloat16*)wkh, (__nv_bfloat16*)wkl, n4);
        n4 = E_ * E_ / 4;
        split_kernel<<<(n4 + 255) / 256, 256>>>(
            W_proj, (__nv_bfloat16*)wph, (__nv_bfloat16*)wpl, n4);
    }

    // 1) QKV projection -> q/k/v bf16 hi/lo (q pre-scaled)
    gemm_cp<1><<<dim3(NKQV / 128, M_ / 128), 256, GSMEM>>>(
        (const __nv_bfloat16*)xh, (const __nv_bfloat16*)xl,
        (const __nv_bfloat16*)wkh, (const __nv_bfloat16*)wkl,
        b_kqv, nullptr, M_, NKQV, E_);

    // 2) V transpose [bh][s][d] -> [bh][d][s]
    vtrans_kernel<<<dim3(S_ / 64, B_ * H_), 256>>>();

    // 3) Tensor-core causal flash attention -> y bf16 hi/lo
    attn_mma<<<dim3(S_ / 128, B_ * H_), 256, ASMEM>>>();

    // 4) Output projection -> d_out (fp32)
    gemm_cp<0><<<dim3(E_ / 128, M_ / 128), 256, GSMEM>>>(
        (const __nv_bfloat16*)yh, (const __nv_bfloat16*)yl,
        (const __nv_bfloat16*)wph, (const __nv_bfloat16*)wpl,
        b_proj, out, M_, E_, E_);
}

// round 5
// speedup vs baseline: 2.3461x; 1.0721x over previous
#include <cuda_runtime.h>
#include <cuda_bf16.h>
#include <cstdint>
#include <math.h>

// Problem constants
constexpr int B_ = 4, S_ = 2048, E_ = 1024, H_ = 16, D_ = 64;
constexpr int M_ = B_ * S_;            // 8192 rows
constexpr int NKQV = 3 * E_;           // 3072

// ---------------------------------------------------------------------------
// Scratch (device globals; bf16 hi/lo pairs)
// ---------------------------------------------------------------------------
__device__ __nv_bfloat16 g_xh[(size_t)M_ * E_],  g_xl[(size_t)M_ * E_];
__device__ __nv_bfloat16 g_wkh[(size_t)NKQV * E_], g_wkl[(size_t)NKQV * E_];
__device__ __nv_bfloat16 g_wph[(size_t)E_ * E_], g_wpl[(size_t)E_ * E_];
__device__ __nv_bfloat16 g_qh[(size_t)B_*H_*S_*D_], g_ql[(size_t)B_*H_*S_*D_];
__device__ __nv_bfloat16 g_kh[(size_t)B_*H_*S_*D_], g_kl[(size_t)B_*H_*S_*D_];
__device__ __nv_bfloat16 g_vh[(size_t)B_*H_*S_*D_], g_vl[(size_t)B_*H_*S_*D_];
__device__ __nv_bfloat16 g_vth[(size_t)B_*H_*S_*D_], g_vtl[(size_t)B_*H_*S_*D_];
__device__ __nv_bfloat16 g_yh[(size_t)M_ * E_],  g_yl[(size_t)M_ * E_];

// ---------------------------------------------------------------------------
// helpers
// ---------------------------------------------------------------------------
__device__ __forceinline__ uint32_t pack_bf16x2(float a, float b) {
    __nv_bfloat16 ha = __float2bfloat16_rn(a);
    __nv_bfloat16 hb = __float2bfloat16_rn(b);
    return (uint32_t)__bfloat16_as_ushort(ha) |
           ((uint32_t)__bfloat16_as_ushort(hb) << 16);
}
__device__ __forceinline__ float bf16_resid(float a) {
    return a - __bfloat162float(__float2bfloat16_rn(a));
}

__device__ __forceinline__ void mma16816(float* c, const uint32_t* a,
                                         uint32_t b0, uint32_t b1) {
    asm volatile(
        "mma.sync.aligned.m16n8k16.row.col.f32.bf16.bf16.f32 "
        "{%0,%1,%2,%3}, {%4,%5,%6,%7}, {%8,%9}, {%0,%1,%2,%3};"
        : "+f"(c[0]), "+f"(c[1]), "+f"(c[2]), "+f"(c[3])
        : "r"(a[0]), "r"(a[1]), "r"(a[2]), "r"(a[3]), "r"(b0), "r"(b1));
}

__device__ __forceinline__ void ldsm_x4(uint32_t* r, uint32_t addr) {
    asm volatile(
        "ldmatrix.sync.aligned.m8n8.x4.shared.b16 {%0,%1,%2,%3}, [%4];"
        : "=r"(r[0]), "=r"(r[1]), "=r"(r[2]), "=r"(r[3]) : "r"(addr));
}

__device__ __forceinline__ uint32_t smem_u32(const void* p) {
    uint32_t a;
    asm("{ .reg .u64 t; cvta.to.shared.u64 t, %1; cvt.u32.u64 %0, t; }"
        : "=r"(a) : "l"(p));
    return a;
}
__device__ __forceinline__ void cp16(uint32_t dst, const void* src) {
    asm volatile("cp.async.ca.shared.global [%0], [%1], 16;"
                 :: "r"(dst), "l"(src));
}
#define CP_COMMIT() asm volatile("cp.async.commit_group;" ::: "memory")
#define CP_WAIT1()  asm volatile("cp.async.wait_group 1;" ::: "memory")
#define CP_WAIT0()  asm volatile("cp.async.wait_group 0;" ::: "memory")

// FMA-pipe exp2 (input in log2 units). ~2e-6 rel err.
__device__ __forceinline__ float exp2p(float x) {
    x = fmaxf(x, -80.f);
    float t = x + 12582912.f;
    int n = __float_as_int(t) - 0x4B400000;
    float r = x - (t - 12582912.f);
    float p = 1.33335581e-3f;
    p = fmaf(p, r, 9.61812911e-3f);
    p = fmaf(p, r, 5.55041087e-2f);
    p = fmaf(p, r, 2.40226507e-1f);
    p = fmaf(p, r, 6.93147180e-1f);
    p = fmaf(p, r, 1.0f);
    return p * __int_as_float((n + 127) << 23);
}

constexpr float QSCALE = 0.125f * 1.44269504088896340736f;

// ---------------------------------------------------------------------------
// split: fp32 -> bf16 hi + lo
// ---------------------------------------------------------------------------
__global__ void split_kernel(const float* __restrict__ src,
                             __nv_bfloat16* __restrict__ hi,
                             __nv_bfloat16* __restrict__ lo, int n4) {
    int i = blockIdx.x * blockDim.x + threadIdx.x;
    if (i >= n4) return;
    float4 v = ((const float4*)src)[i];
    ((uint2*)hi)[i] = make_uint2(pack_bf16x2(v.x, v.y), pack_bf16x2(v.z, v.w));
    ((uint2*)lo)[i] = make_uint2(
        pack_bf16x2(bf16_resid(v.x), bf16_resid(v.y)),
        pack_bf16x2(bf16_resid(v.z), bf16_resid(v.w)));
}

// ---------------------------------------------------------------------------
// GEMM: C[M,N] = (Ah+Al)[M,K] @ (Bh+Bl)[N,K]^T + bias
// 128x128x32 tiles, 8 warps, 3-stage cp.async pipeline, ldmatrix fragments,
// one barrier per stage. 3-MMA hi/lo split.
// ---------------------------------------------------------------------------
constexpr int GBK = 32;
constexpr int GSTR = 40;                     // padded bf16 stride (80B rows)
constexpr int GTILE_E = 128 * GSTR;          // 5120
constexpr int GSTAGE_E = 4 * GTILE_E;        // 20480
constexpr int GSMEM = 3 * GSTAGE_E * 2;      // 122880 B

template <int MODE>
__global__ __launch_bounds__(256) void gemm_cp(
    const __nv_bfloat16* __restrict__ Ah, const __nv_bfloat16* __restrict__ Al,
    const __nv_bfloat16* __restrict__ Bh, const __nv_bfloat16* __restrict__ Bl,
    const float* __restrict__ bias, float* __restrict__ C,
    int M, int N, int K)
{
    extern __shared__ __nv_bfloat16 smb[];
    const uint32_t smb_u = smem_u32(smb);
    const int tid = threadIdx.x;
    const int lane = tid & 31;
    const int w = tid >> 5;
    const int wm = w & 1, wn = w >> 1;
    const int g = lane >> 2, t = lane & 3;
    const int m0 = blockIdx.y * 128;
    const int n0 = blockIdx.x * 128;

    const __nv_bfloat16* bases[4] = {
        Ah + (size_t)m0 * K, Al + (size_t)m0 * K,
        Bh + (size_t)n0 * K, Bl + (size_t)n0 * K };

    const int nsteps = K / GBK;

    auto issue = [&](int s) {
        __nv_bfloat16* st = smb + (s % 3) * GSTAGE_E;
        const int k0 = s * GBK;
#pragma unroll
        for (int c = 0; c < 8; c++) {
            int ci = tid + c * 256;
            int arr = ci >> 9;
            int idx = ci & 511;
            int r = idx >> 2, ch = idx & 3;
            cp16(smem_u32(st + arr * GTILE_E + r * GSTR + ch * 8),
                 bases[arr] + (size_t)r * K + k0 + ch * 8);
        }
        CP_COMMIT();
    };

    // ldmatrix per-lane address offsets (element units)
    //  A (16x16 per mt):  row = (lane&15), kchunk = (lane>>4)*8
    //  B (2 nt per x4):   row = ((lane>>4)&1)*8 + (lane&7), kchunk = ((lane>>3)&1)*8
    const uint32_t a_off =
        (uint32_t)((wm * 64 + (lane & 15)) * GSTR + (lane >> 4) * 8) * 2;
    const uint32_t b_off =
        (uint32_t)((wn * 32 + ((lane >> 4) & 1) * 8 + (lane & 7)) * GSTR +
                   ((lane >> 3) & 1) * 8) * 2;

    float acc[4][4][4];
#pragma unroll
    for (int i = 0; i < 4; i++)
#pragma unroll
        for (int j = 0; j < 4; j++)
#pragma unroll
            for (int e = 0; e < 4; e++) acc[i][j][e] = 0.f;

    issue(0);
    issue(1);

    for (int s = 0; s < nsteps; s++) {
        if (s + 1 < nsteps) { CP_WAIT1(); } else { CP_WAIT0(); }
        __syncthreads();
        if (s + 2 < nsteps) issue(s + 2);

        const uint32_t st = smb_u + (uint32_t)((s % 3) * GSTAGE_E) * 2;
        const uint32_t uAh = st;
        const uint32_t uAl = st + GTILE_E * 2;
        const uint32_t uBh = st + 2 * GTILE_E * 2;
        const uint32_t uBl = st + 3 * GTILE_E * 2;

#pragma unroll
        for (int ks = 0; ks < 2; ks++) {
            const uint32_t kso = (uint32_t)(ks * 16) * 2;
            uint32_t ah[4][4], al[4][4];
#pragma unroll
            for (int mt = 0; mt < 4; mt++) {
                const uint32_t ro = (uint32_t)(mt * 16 * GSTR) * 2;
                ldsm_x4(ah[mt], uAh + a_off + ro + kso);
                ldsm_x4(al[mt], uAl + a_off + ro + kso);
            }
#pragma unroll
            for (int p = 0; p < 2; p++) {
                const uint32_t ro = (uint32_t)(p * 16 * GSTR) * 2;
                uint32_t bh[4], bl[4];
                ldsm_x4(bh, uBh + b_off + ro + kso);
                ldsm_x4(bl, uBl + b_off + ro + kso);
#pragma unroll
                for (int mt = 0; mt < 4; mt++) {
                    mma16816(acc[mt][2 * p], ah[mt], bh[0], bh[1]);
                    mma16816(acc[mt][2 * p], al[mt], bh[0], bh[1]);
                    mma16816(acc[mt][2 * p], ah[mt], bl[0], bl[1]);
                    mma16816(acc[mt][2 * p + 1], ah[mt], bh[2], bh[3]);
                    mma16816(acc[mt][2 * p + 1], al[mt], bh[2], bh[3]);
                    mma16816(acc[mt][2 * p + 1], ah[mt], bl[2], bl[3]);
                }
            }
        }
    }

    // ---- epilogue --------------------------------------------------------
#pragma unroll
    for (int mt = 0; mt < 4; mt++) {
#pragma unroll
        for (int nt = 0; nt < 4; nt++) {
            const int m = m0 + wm * 64 + mt * 16 + g;
            const int n = n0 + wn * 32 + nt * 8 + t * 2;
            const float* c = acc[mt][nt];
            float2 bv = *(const float2*)(bias + n);
            if (MODE == 0) {
                *(float2*)(C + (size_t)m * N + n) =
                    make_float2(c[0] + bv.x, c[1] + bv.y);
                *(float2*)(C + (size_t)(m + 8) * N + n) =
                    make_float2(c[2] + bv.x, c[3] + bv.y);
            } else {
                const int which = n >> 10;
                const int h = (n >> 6) & 15;
                const int d = n & 63;
                const float sc = (which == 1) ? QSCALE : 1.0f;
                __nv_bfloat16* dh = (which == 0 ? g_kh : which == 1 ? g_qh : g_vh);
                __nv_bfloat16* dl = (which == 0 ? g_kl : which == 1 ? g_ql : g_vl);
#pragma unroll
                for (int rr = 0; rr < 2; rr++) {
                    const int mm = m + rr * 8;
                    const int b = mm >> 11, s = mm & 2047;
                    const size_t off =
                        ((((size_t)b * H_ + h) * S_) + s) * D_ + d;
                    float v0 = (c[rr * 2 + 0] + bv.x) * sc;
                    float v1 = (c[rr * 2 + 1] + bv.y) * sc;
                    *(uint32_t*)(dh + off) = pack_bf16x2(v0, v1);
                    *(uint32_t*)(dl + off) =
                        pack_bf16x2(bf16_resid(v0), bf16_resid(v1));
                }
            }
        }
    }
}

// ---------------------------------------------------------------------------
// V transpose: [bh][s][d] -> [bh][d][s], hi and lo
// ---------------------------------------------------------------------------
__global__ __launch_bounds__(256) void vtrans_kernel() {
    __shared__ __nv_bfloat16 tile[64][72];
    const int tid = threadIdx.x;
    const int st = blockIdx.x;
    const int bh = blockIdx.y;

    const __nv_bfloat16* srcs[2] = {
        g_vh + ((size_t)bh * S_ + st * 64) * D_,
        g_vl + ((size_t)bh * S_ + st * 64) * D_ };
    __nv_bfloat16* dsts[2] = {
        g_vth + (size_t)bh * D_ * S_ + st * 64,
        g_vtl + (size_t)bh * D_ * S_ + st * 64 };

    for (int a = 0; a < 2; a++) {
        __syncthreads();
#pragma unroll
        for (int c = 0; c < 8; c++) {
            int ci = tid + c * 256;
            int r = ci >> 5, ch = ci & 31;
            *(uint32_t*)&tile[r][ch * 2] =
                *(const uint32_t*)(srcs[a] + (size_t)r * D_ + ch * 2);
        }
        __syncthreads();
#pragma unroll
        for (int c = 0; c < 8; c++) {
            int ci = tid + c * 256;
            int d = ci >> 5, s2 = (ci & 31) * 2;
            uint32_t o = (uint32_t)__bfloat16_as_ushort(tile[s2][d]) |
                         ((uint32_t)__bfloat16_as_ushort(tile[s2 + 1][d]) << 16);
            *(uint32_t*)(dsts[a] + (size_t)d * S_ + s2) = o;
        }
    }
}

// ---------------------------------------------------------------------------
// Tensor-core causal flash attention. CTA = (q-tile 128, bh), 8 warps.
// K-tiles of 64; 3-buffer cp.async prefetch 2 ahead; ldmatrix K/V fragments;
// FMA-pipe exp2; one barrier per k-tile.
// ---------------------------------------------------------------------------
constexpr int ASTR = 72;
constexpr int AQ_E = 2 * 128 * ASTR;            // q hi+lo staging
constexpr int AKT_E = 64 * ASTR;                // one 64x64 operand tile
constexpr int AKSTAGE_E = 4 * AKT_E;            // kh,kl,vth,vtl
constexpr int ASMEM = (AQ_E + 3 * AKSTAGE_E) * 2;   // 147456 B

__global__ __launch_bounds__(256) void attn_mma() {
    extern __shared__ __nv_bfloat16 sma[];
    const uint32_t sma_u = smem_u32(sma);
    const int tid = threadIdx.x;
    const int lane = tid & 31;
    const int w = tid >> 5;
    const int g = lane >> 2, t = lane & 3;
    const int qt = (S_ / 128 - 1) - blockIdx.x;
    const int bh = blockIdx.y;
    const int nkt = 2 * qt + 2;

    __nv_bfloat16* QH = sma;
    __nv_bfloat16* QL = sma + 128 * ASTR;
    const uint32_t KV0_u = sma_u + AQ_E * 2;

    // ---- stage Q
    {
        const __nv_bfloat16* qsrc[2] = {
            g_qh + ((size_t)bh * S_ + qt * 128) * D_,
            g_ql + ((size_t)bh * S_ + qt * 128) * D_ };
#pragma unroll
        for (int c = 0; c < 8; c++) {
            int ci = tid + c * 256;
            int arr = ci >> 10;
            int idx = ci & 1023;
            int r = idx >> 3, ch = idx & 7;
            cp16(smem_u32(sma + arr * (128 * ASTR) + r * ASTR + ch * 8),
                 qsrc[arr] + (size_t)r * D_ + ch * 8);
        }
        CP_COMMIT();
    }

    auto issueKV = [&](int kt) {
        uint32_t st = KV0_u + (uint32_t)((kt % 3) * AKSTAGE_E) * 2;
        const __nv_bfloat16* bases[4] = {
            g_kh + ((size_t)bh * S_ + kt * 64) * D_,
            g_kl + ((size_t)bh * S_ + kt * 64) * D_,
            g_vth + (size_t)bh * D_ * S_ + kt * 64,
            g_vtl + (size_t)bh * D_ * S_ + kt * 64 };
#pragma unroll
        for (int c = 0; c < 8; c++) {
            int ci = tid + c * 256;
            int arr = ci >> 9;
            int idx = ci & 511;
            int r = idx >> 3, ch = idx & 7;
            const size_t rs = (arr < 2) ? (size_t)D_ : (size_t)S_;
            cp16(st + (uint32_t)(arr * AKT_E + r * ASTR + ch * 8) * 2,
                 bases[arr] + (size_t)r * rs + ch * 8);
        }
        CP_COMMIT();
    };

    issueKV(0);
    CP_WAIT1();            // Q (oldest group) complete
    __syncthreads();

    // ---- Q fragments (registers, whole CTA lifetime)
    uint32_t qfh[4][4], qfl[4][4];
#pragma unroll
    for (int ks = 0; ks < 4; ks++) {
        const int kb = ks * 16 + t * 2;
        const int r0 = (w * 16 + g) * ASTR;
        qfh[ks][0] = *(const uint32_t*)(QH + r0 + kb);
        qfh[ks][1] = *(const uint32_t*)(QH + r0 + 8 * ASTR + kb);
        qfh[ks][2] = *(const uint32_t*)(QH + r0 + kb + 8);
        qfh[ks][3] = *(const uint32_t*)(QH + r0 + 8 * ASTR + kb + 8);
        qfl[ks][0] = *(const uint32_t*)(QL + r0 + kb);
        qfl[ks][1] = *(const uint32_t*)(QL + r0 + 8 * ASTR + kb);
        qfl[ks][2] = *(const uint32_t*)(QL + r0 + kb + 8);
        qfl[ks][3] = *(const uint32_t*)(QL + r0 + 8 * ASTR + kb + 8);
    }

    issueKV(1);

    // B-fragment ldmatrix lane offset (covers 2 nt per x4)
    const uint32_t bfrag_off =
        (uint32_t)((((lane >> 4) & 1) * 8 + (lane & 7)) * ASTR +
                   ((lane >> 3) & 1) * 8) * 2;

    float o[8][4];
#pragma unroll
    for (int nt = 0; nt < 8; nt++)
#pragma unroll
        for (int e = 0; e < 4; e++) o[nt][e] = 0.f;
    float m0 = -1e30f, m1 = -1e30f, l0 = 0.f, l1 = 0.f;

    const int row0 = qt * 128 + w * 16 + g;
    const int row1 = row0 + 8;

    for (int kt = 0; kt < nkt; kt++) {
        if (kt + 1 < nkt) { CP_WAIT1(); } else { CP_WAIT0(); }
        __syncthreads();
        if (kt + 2 < nkt) issueKV(kt + 2);

        const uint32_t st = KV0_u + (uint32_t)((kt % 3) * AKSTAGE_E) * 2;
        const uint32_t uKH = st;
        const uint32_t uKL = st + AKT_E * 2;
        const uint32_t uVH = st + 2 * AKT_E * 2;
        const uint32_t uVL = st + 3 * AKT_E * 2;

        // ---- S = Q @ K^T (3-split, ldmatrix)
        float sc[8][4];
#pragma unroll
        for (int nt = 0; nt < 8; nt++)
#pragma unroll
            for (int e = 0; e < 4; e++) sc[nt][e] = 0.f;

#pragma unroll
        for (int ntp = 0; ntp < 4; ntp++) {
            const uint32_t ro = (uint32_t)(ntp * 16 * ASTR) * 2;
#pragma unroll
            for (int ks = 0; ks < 4; ks++) {
                const uint32_t kso = (uint32_t)(ks * 16) * 2;
                uint32_t bh4[4], bl4[4];
                ldsm_x4(bh4, uKH + bfrag_off + ro + kso);
                ldsm_x4(bl4, uKL + bfrag_off + ro + kso);
                mma16816(sc[2 * ntp], qfh[ks], bh4[0], bh4[1]);
                mma16816(sc[2 * ntp], qfl[ks], bh4[0], bh4[1]);
                mma16816(sc[2 * ntp], qfh[ks], bl4[0], bl4[1]);
                mma16816(sc[2 * ntp + 1], qfh[ks], bh4[2], bh4[3]);
                mma16816(sc[2 * ntp + 1], qfl[ks], bh4[2], bh4[3]);
                mma16816(sc[2 * ntp + 1], qfh[ks], bl4[2], bl4[3]);
            }
        }

        // ---- causal mask
        if (kt >= 2 * qt) {
#pragma unroll
            for (int nt = 0; nt < 8; nt++) {
                const int c0 = kt * 64 + nt * 8 + 2 * t;
                if (c0 > row0)     sc[nt][0] = -1e30f;
                if (c0 + 1 > row0) sc[nt][1] = -1e30f;
                if (c0 > row1)     sc[nt][2] = -1e30f;
                if (c0 + 1 > row1) sc[nt][3] = -1e30f;
            }
        }

        // ---- online softmax (base-2, FMA pipe)
        float mx0 = -1e30f, mx1 = -1e30f;
#pragma unroll
        for (int nt = 0; nt < 8; nt++) {
            mx0 = fmaxf(mx0, fmaxf(sc[nt][0], sc[nt][1]));
            mx1 = fmaxf(mx1, fmaxf(sc[nt][2], sc[nt][3]));
        }
        mx0 = fmaxf(mx0, __shfl_xor_sync(0xffffffffu, mx0, 1));
        mx0 = fmaxf(mx0, __shfl_xor_sync(0xffffffffu, mx0, 2));
        mx1 = fmaxf(mx1, __shfl_xor_sync(0xffffffffu, mx1, 1));
        mx1 = fmaxf(mx1, __shfl_xor_sync(0xffffffffu, mx1, 2));

        const float mn0 = fmaxf(m0, mx0), mn1 = fmaxf(m1, mx1);
        const float a0 = exp2p(m0 - mn0), a1 = exp2p(m1 - mn1);
        m0 = mn0; m1 = mn1;

        float rs0 = 0.f, rs1 = 0.f;
#pragma unroll
        for (int nt = 0; nt < 8; nt++) {
            sc[nt][0] = exp2p(sc[nt][0] - mn0);
            sc[nt][1] = exp2p(sc[nt][1] - mn0);
            sc[nt][2] = exp2p(sc[nt][2] - mn1);
            sc[nt][3] = exp2p(sc[nt][3] - mn1);
            rs0 += sc[nt][0] + sc[nt][1];
            rs1 += sc[nt][2] + sc[nt][3];
        }
        rs0 += __shfl_xor_sync(0xffffffffu, rs0, 1);
        rs0 += __shfl_xor_sync(0xffffffffu, rs0, 2);
        rs1 += __shfl_xor_sync(0xffffffffu, rs1, 1);
        rs1 += __shfl_xor_sync(0xffffffffu, rs1, 2);
        l0 = l0 * a0 + rs0;
        l1 = l1 * a1 + rs1;

#pragma unroll
        for (int nt = 0; nt < 8; nt++) {
            o[nt][0] *= a0; o[nt][1] *= a0;
            o[nt][2] *= a1; o[nt][3] *= a1;
        }

        // ---- P fragments (FA layout) + hi/lo split
        uint32_t pfh[4][4], pfl[4][4];
#pragma unroll
        for (int ks = 0; ks < 4; ks++) {
            const float* p0 = sc[2 * ks];
            const float* p1 = sc[2 * ks + 1];
            pfh[ks][0] = pack_bf16x2(p0[0], p0[1]);
            pfh[ks][1] = pack_bf16x2(p0[2], p0[3]);
            pfh[ks][2] = pack_bf16x2(p1[0], p1[1]);
            pfh[ks][3] = pack_bf16x2(p1[2], p1[3]);
            pfl[ks][0] = pack_bf16x2(bf16_resid(p0[0]), bf16_resid(p0[1]));
            pfl[ks][1] = pack_bf16x2(bf16_resid(p0[2]), bf16_resid(p0[3]));
            pfl[ks][2] = pack_bf16x2(bf16_resid(p1[0]), bf16_resid(p1[1]));
            pfl[ks][3] = pack_bf16x2(bf16_resid(p1[2]), bf16_resid(p1[3]));
        }

        // ---- O += P @ V (3-split, ldmatrix; V^T staged [d][s])
#pragma unroll
        for (int ntp = 0; ntp < 4; ntp++) {
            const uint32_t ro = (uint32_t)(ntp * 16 * ASTR) * 2;
#pragma unroll
            for (int ks = 0; ks < 4; ks++) {
                const uint32_t kso = (uint32_t)(ks * 16) * 2;
                uint32_t vh4[4], vl4[4];
                ldsm_x4(vh4, uVH + bfrag_off + ro + kso);
                ldsm_x4(vl4, uVL + bfrag_off + ro + kso);
                mma16816(o[2 * ntp], pfh[ks], vh4[0], vh4[1]);
                mma16816(o[2 * ntp], pfl[ks], vh4[0], vh4[1]);
                mma16816(o[2 * ntp], pfh[ks], vl4[0], vl4[1]);
                mma16816(o[2 * ntp + 1], pfh[ks], vh4[2], vh4[3]);
                mma16816(o[2 * ntp + 1], pfl[ks], vh4[2], vh4[3]);
                mma16816(o[2 * ntp + 1], pfh[ks], vl4[2], vl4[3]);
            }
        }
    }

    // ---- epilogue: y = O / l, bf16 hi/lo, [b][s][h*64+d]
    const float inv0 = 1.0f / l0, inv1 = 1.0f / l1;
    const int b = bh >> 4, h = bh & 15;
#pragma unroll
    for (int nt = 0; nt < 8; nt++) {
        const int e = h * 64 + nt * 8 + 2 * t;
        {
            const size_t off = ((size_t)b * S_ + row0) * E_ + e;
            float v0 = o[nt][0] * inv0, v1 = o[nt][1] * inv0;
            *(uint32_t*)(g_yh + off) = pack_bf16x2(v0, v1);
            *(uint32_t*)(g_yl + off) =
                pack_bf16x2(bf16_resid(v0), bf16_resid(v1));
        }
        {
            const size_t off = ((size_t)b * S_ + row1) * E_ + e;
            float v0 = o[nt][2] * inv1, v1 = o[nt][3] * inv1;
            *(uint32_t*)(g_yh + off) = pack_bf16x2(v0, v1);
            *(uint32_t*)(g_yl + off) =
                pack_bf16x2(bf16_resid(v0), bf16_resid(v1));
        }
    }
}

// ---------------------------------------------------------------------------
// Launch
// ---------------------------------------------------------------------------
extern "C" void kernel_launch(void* const* d_in, const int* in_sizes, int n_in,
                              void* d_out, int out_size)
{
    const float* x      = (const float*)d_in[0];
    const float* W_kqv  = (const float*)d_in[1];
    const float* b_kqv  = (const float*)d_in[2];
    const float* W_proj = (const float*)d_in[3];
    const float* b_proj = (const float*)d_in[4];
    float* out = (float*)d_out;

    void *xh, *xl, *wkh, *wkl, *wph, *wpl, *yh, *yl;
    cudaGetSymbolAddress(&xh, g_xh);   cudaGetSymbolAddress(&xl, g_xl);
    cudaGetSymbolAddress(&wkh, g_wkh); cudaGetSymbolAddress(&wkl, g_wkl);
    cudaGetSymbolAddress(&wph, g_wph); cudaGetSymbolAddress(&wpl, g_wpl);
    cudaGetSymbolAddress(&yh, g_yh);   cudaGetSymbolAddress(&yl, g_yl);

    cudaFuncSetAttribute(gemm_cp<0>, cudaFuncAttributeMaxDynamicSharedMemorySize, GSMEM);
    cudaFuncSetAttribute(gemm_cp<1>, cudaFuncAttributeMaxDynamicSharedMemorySize, GSMEM);
    cudaFuncSetAttribute(attn_mma,   cudaFuncAttributeMaxDynamicSharedMemorySize, ASMEM);

    // 0) split inputs to bf16 hi/lo
    {
        int n4 = M_ * E_ / 4;
        split_kernel<<<(n4 + 255) / 256, 256>>>(
            x, (__nv_bfloat16*)xh, (__nv_bfloat16*)xl, n4);
        n4 = NKQV * E_ / 4;
        split_kernel<<<(n4 + 255) / 256, 256>>>(
            W_kqv, (__nv_bfloat16*)wkh, (__nv_bfloat16*)wkl, n4);
        n4 = E_ * E_ / 4;
        split_kernel<<<(n4 + 255) / 256, 256>>>(
            W_proj, (__nv_bfloat16*)wph, (__nv_bfloat16*)wpl, n4);
    }

    // 1) QKV projection -> q/k/v bf16 hi/lo (q pre-scaled)
    gemm_cp<1><<<dim3(NKQV / 128, M_ / 128), 256, GSMEM>>>(
        (const __nv_bfloat16*)xh, (const __nv_bfloat16*)xl,
        (const __nv_bfloat16*)wkh, (const __nv_bfloat16*)wkl,
        b_kqv, nullptr, M_, NKQV, E_);

    // 2) V transpose [bh][s][d] -> [bh][d][s]
    vtrans_kernel<<<dim3(S_ / 64, B_ * H_), 256>>>();

    // 3) Tensor-core causal flash attention -> y bf16 hi/lo
    attn_mma<<<dim3(S_ / 128, B_ * H_), 256, ASMEM>>>();

    // 4) Output projection -> d_out (fp32)
    gemm_cp<0><<<dim3(E_ / 128, M_ / 128), 256, GSMEM>>>(
        (const __nv_bfloat16*)yh, (const __nv_bfloat16*)yl,
        (const __nv_bfloat16*)wph, (const __nv_bfloat16*)wpl,
        b_proj, out, M_, E_, E_);
}

// round 6
// speedup vs baseline: 2.4825x; 1.0581x over previous
#include <cuda_runtime.h>
#include <cuda_bf16.h>
#include <cstdint>
#include <math.h>

// Problem constants
constexpr int B_ = 4, S_ = 2048, E_ = 1024, H_ = 16, D_ = 64;
constexpr int M_ = B_ * S_;            // 8192 rows
constexpr int NKQV = 3 * E_;           // 3072

// ---------------------------------------------------------------------------
// Scratch (device globals; bf16 hi/lo pairs)
// ---------------------------------------------------------------------------
__device__ __nv_bfloat16 g_xh[(size_t)M_ * E_],  g_xl[(size_t)M_ * E_];
__device__ __nv_bfloat16 g_wkh[(size_t)NKQV * E_], g_wkl[(size_t)NKQV * E_];
__device__ __nv_bfloat16 g_wph[(size_t)E_ * E_], g_wpl[(size_t)E_ * E_];
__device__ __nv_bfloat16 g_qh[(size_t)B_*H_*S_*D_], g_ql[(size_t)B_*H_*S_*D_];
__device__ __nv_bfloat16 g_kh[(size_t)B_*H_*S_*D_], g_kl[(size_t)B_*H_*S_*D_];
__device__ __nv_bfloat16 g_vh[(size_t)B_*H_*S_*D_], g_vl[(size_t)B_*H_*S_*D_];
__device__ __nv_bfloat16 g_vth[(size_t)B_*H_*S_*D_], g_vtl[(size_t)B_*H_*S_*D_];
__device__ __nv_bfloat16 g_yh[(size_t)M_ * E_],  g_yl[(size_t)M_ * E_];

// ---------------------------------------------------------------------------
// helpers
// ---------------------------------------------------------------------------
__device__ __forceinline__ uint32_t pack_bf16x2(float a, float b) {
    __nv_bfloat16 ha = __float2bfloat16_rn(a);
    __nv_bfloat16 hb = __float2bfloat16_rn(b);
    return (uint32_t)__bfloat16_as_ushort(ha) |
           ((uint32_t)__bfloat16_as_ushort(hb) << 16);
}
__device__ __forceinline__ float bf16_resid(float a) {
    return a - __bfloat162float(__float2bfloat16_rn(a));
}

__device__ __forceinline__ void mma16816(float* c, const uint32_t* a,
                                         uint32_t b0, uint32_t b1) {
    asm volatile(
        "mma.sync.aligned.m16n8k16.row.col.f32.bf16.bf16.f32 "
        "{%0,%1,%2,%3}, {%4,%5,%6,%7}, {%8,%9}, {%0,%1,%2,%3};"
        : "+f"(c[0]), "+f"(c[1]), "+f"(c[2]), "+f"(c[3])
        : "r"(a[0]), "r"(a[1]), "r"(a[2]), "r"(a[3]), "r"(b0), "r"(b1));
}

__device__ __forceinline__ void ldsm_x4(uint32_t* r, uint32_t addr) {
    asm volatile(
        "ldmatrix.sync.aligned.m8n8.x4.shared.b16 {%0,%1,%2,%3}, [%4];"
        : "=r"(r[0]), "=r"(r[1]), "=r"(r[2]), "=r"(r[3]) : "r"(addr));
}

__device__ __forceinline__ uint32_t smem_u32(const void* p) {
    uint32_t a;
    asm("{ .reg .u64 t; cvta.to.shared.u64 t, %1; cvt.u32.u64 %0, t; }"
        : "=r"(a) : "l"(p));
    return a;
}
__device__ __forceinline__ void cp16(uint32_t dst, const void* src) {
    asm volatile("cp.async.ca.shared.global [%0], [%1], 16;"
                 :: "r"(dst), "l"(src));
}
#define CP_COMMIT() asm volatile("cp.async.commit_group;" ::: "memory")
#define CP_WAIT1()  asm volatile("cp.async.wait_group 1;" ::: "memory")
#define CP_WAIT0()  asm volatile("cp.async.wait_group 0;" ::: "memory")

// FMA-pipe exp2 (input in log2 units). ~2e-6 rel err.
__device__ __forceinline__ float exp2p(float x) {
    x = fmaxf(x, -80.f);
    float t = x + 12582912.f;
    int n = __float_as_int(t) - 0x4B400000;
    float r = x - (t - 12582912.f);
    float p = 1.33335581e-3f;
    p = fmaf(p, r, 9.61812911e-3f);
    p = fmaf(p, r, 5.55041087e-2f);
    p = fmaf(p, r, 2.40226507e-1f);
    p = fmaf(p, r, 6.93147180e-1f);
    p = fmaf(p, r, 1.0f);
    return p * __int_as_float((n + 127) << 23);
}

constexpr float QSCALE = 0.125f * 1.44269504088896340736f;

// ---------------------------------------------------------------------------
// split: fp32 -> bf16 hi + lo
// ---------------------------------------------------------------------------
__global__ void split_kernel(const float* __restrict__ src,
                             __nv_bfloat16* __restrict__ hi,
                             __nv_bfloat16* __restrict__ lo, int n4) {
    int i = blockIdx.x * blockDim.x + threadIdx.x;
    if (i >= n4) return;
    float4 v = ((const float4*)src)[i];
    ((uint2*)hi)[i] = make_uint2(pack_bf16x2(v.x, v.y), pack_bf16x2(v.z, v.w));
    ((uint2*)lo)[i] = make_uint2(
        pack_bf16x2(bf16_resid(v.x), bf16_resid(v.y)),
        pack_bf16x2(bf16_resid(v.z), bf16_resid(v.w)));
}

// ---------------------------------------------------------------------------
// GEMM: C[M,N] = (Ah+Al)[M,K] @ (Bh+Bl)[N,K]^T + bias
// 128x128x32 tiles, 8 warps, 2-stage cp.async pipeline (2 CTAs/SM),
// ldmatrix fragments, split-major MMA issue order.
// ---------------------------------------------------------------------------
constexpr int GBK = 32;
constexpr int GSTR = 40;                     // padded bf16 stride (80B rows)
constexpr int GTILE_E = 128 * GSTR;          // 5120
constexpr int GSTAGE_E = 4 * GTILE_E;        // 20480
constexpr int GSMEM = 2 * GSTAGE_E * 2;      // 81920 B -> 2 CTAs/SM

template <int MODE>
__global__ __launch_bounds__(256, 2) void gemm_cp(
    const __nv_bfloat16* __restrict__ Ah, const __nv_bfloat16* __restrict__ Al,
    const __nv_bfloat16* __restrict__ Bh, const __nv_bfloat16* __restrict__ Bl,
    const float* __restrict__ bias, float* __restrict__ C,
    int M, int N, int K)
{
    extern __shared__ __nv_bfloat16 smb[];
    const uint32_t smb_u = smem_u32(smb);
    const int tid = threadIdx.x;
    const int lane = tid & 31;
    const int w = tid >> 5;
    const int wm = w & 1, wn = w >> 1;
    const int g = lane >> 2, t = lane & 3;
    const int m0 = blockIdx.y * 128;
    const int n0 = blockIdx.x * 128;

    const __nv_bfloat16* bases[4] = {
        Ah + (size_t)m0 * K, Al + (size_t)m0 * K,
        Bh + (size_t)n0 * K, Bl + (size_t)n0 * K };

    const int nsteps = K / GBK;

    auto issue = [&](int s) {
        __nv_bfloat16* st = smb + (s & 1) * GSTAGE_E;
        const int k0 = s * GBK;
#pragma unroll
        for (int c = 0; c < 8; c++) {
            int ci = tid + c * 256;
            int arr = ci >> 9;
            int idx = ci & 511;
            int r = idx >> 2, ch = idx & 3;
            cp16(smem_u32(st + arr * GTILE_E + r * GSTR + ch * 8),
                 bases[arr] + (size_t)r * K + k0 + ch * 8);
        }
        CP_COMMIT();
    };

    const uint32_t a_off =
        (uint32_t)((wm * 64 + (lane & 15)) * GSTR + (lane >> 4) * 8) * 2;
    const uint32_t b_off =
        (uint32_t)((wn * 32 + ((lane >> 4) & 1) * 8 + (lane & 7)) * GSTR +
                   ((lane >> 3) & 1) * 8) * 2;

    float acc[4][4][4];
#pragma unroll
    for (int i = 0; i < 4; i++)
#pragma unroll
        for (int j = 0; j < 4; j++)
#pragma unroll
            for (int e = 0; e < 4; e++) acc[i][j][e] = 0.f;

    issue(0);
    issue(1);

    for (int s = 0; s < nsteps; s++) {
        if (s + 1 < nsteps) { CP_WAIT1(); } else { CP_WAIT0(); }
        __syncthreads();

        const uint32_t st = smb_u + (uint32_t)((s & 1) * GSTAGE_E) * 2;
        const uint32_t uAh = st;
        const uint32_t uAl = st + GTILE_E * 2;
        const uint32_t uBh = st + 2 * GTILE_E * 2;
        const uint32_t uBl = st + 3 * GTILE_E * 2;

#pragma unroll
        for (int ks = 0; ks < 2; ks++) {
            const uint32_t kso = (uint32_t)(ks * 16) * 2;
            uint32_t ah[4][4], al[4][4];
#pragma unroll
            for (int mt = 0; mt < 4; mt++) {
                const uint32_t ro = (uint32_t)(mt * 16 * GSTR) * 2;
                ldsm_x4(ah[mt], uAh + a_off + ro + kso);
                ldsm_x4(al[mt], uAl + a_off + ro + kso);
            }
#pragma unroll
            for (int p = 0; p < 2; p++) {
                const uint32_t ro = (uint32_t)(p * 16 * GSTR) * 2;
                uint32_t bh[4], bl[4];
                ldsm_x4(bh, uBh + b_off + ro + kso);
                ldsm_x4(bl, uBl + b_off + ro + kso);
                // split-major issue: same accumulator revisited at distance 4
#pragma unroll
                for (int mt = 0; mt < 4; mt++)
                    mma16816(acc[mt][2 * p], ah[mt], bh[0], bh[1]);
#pragma unroll
                for (int mt = 0; mt < 4; mt++)
                    mma16816(acc[mt][2 * p + 1], ah[mt], bh[2], bh[3]);
#pragma unroll
                for (int mt = 0; mt < 4; mt++)
                    mma16816(acc[mt][2 * p], al[mt], bh[0], bh[1]);
#pragma unroll
                for (int mt = 0; mt < 4; mt++)
                    mma16816(acc[mt][2 * p + 1], al[mt], bh[2], bh[3]);
#pragma unroll
                for (int mt = 0; mt < 4; mt++)
                    mma16816(acc[mt][2 * p], ah[mt], bl[0], bl[1]);
#pragma unroll
                for (int mt = 0; mt < 4; mt++)
                    mma16816(acc[mt][2 * p + 1], ah[mt], bl[2], bl[3]);
            }
        }

        __syncthreads();                 // all reads of buf s&1 done
        if (s + 2 < nsteps) issue(s + 2);
    }

    // ---- epilogue --------------------------------------------------------
#pragma unroll
    for (int mt = 0; mt < 4; mt++) {
#pragma unroll
        for (int nt = 0; nt < 4; nt++) {
            const int m = m0 + wm * 64 + mt * 16 + g;
            const int n = n0 + wn * 32 + nt * 8 + t * 2;
            const float* c = acc[mt][nt];
            float2 bv = *(const float2*)(bias + n);
            if (MODE == 0) {
                *(float2*)(C + (size_t)m * N + n) =
                    make_float2(c[0] + bv.x, c[1] + bv.y);
                *(float2*)(C + (size_t)(m + 8) * N + n) =
                    make_float2(c[2] + bv.x, c[3] + bv.y);
            } else {
                const int which = n >> 10;
                const int h = (n >> 6) & 15;
                const int d = n & 63;
                const float sc = (which == 1) ? QSCALE : 1.0f;
                __nv_bfloat16* dh = (which == 0 ? g_kh : which == 1 ? g_qh : g_vh);
                __nv_bfloat16* dl = (which == 0 ? g_kl : which == 1 ? g_ql : g_vl);
#pragma unroll
                for (int rr = 0; rr < 2; rr++) {
                    const int mm = m + rr * 8;
                    const int b = mm >> 11, s = mm & 2047;
                    const size_t off =
                        ((((size_t)b * H_ + h) * S_) + s) * D_ + d;
                    float v0 = (c[rr * 2 + 0] + bv.x) * sc;
                    float v1 = (c[rr * 2 + 1] + bv.y) * sc;
                    *(uint32_t*)(dh + off) = pack_bf16x2(v0, v1);
                    *(uint32_t*)(dl + off) =
                        pack_bf16x2(bf16_resid(v0), bf16_resid(v1));
                }
            }
        }
    }
}

// ---------------------------------------------------------------------------
// V transpose: [bh][s][d] -> [bh][d][s], hi and lo
// ---------------------------------------------------------------------------
__global__ __launch_bounds__(256) void vtrans_kernel() {
    __shared__ __nv_bfloat16 tile[64][72];
    const int tid = threadIdx.x;
    const int st = blockIdx.x;
    const int bh = blockIdx.y;

    const __nv_bfloat16* srcs[2] = {
        g_vh + ((size_t)bh * S_ + st * 64) * D_,
        g_vl + ((size_t)bh * S_ + st * 64) * D_ };
    __nv_bfloat16* dsts[2] = {
        g_vth + (size_t)bh * D_ * S_ + st * 64,
        g_vtl + (size_t)bh * D_ * S_ + st * 64 };

    for (int a = 0; a < 2; a++) {
        __syncthreads();
#pragma unroll
        for (int c = 0; c < 8; c++) {
            int ci = tid + c * 256;
            int r = ci >> 5, ch = ci & 31;
            *(uint32_t*)&tile[r][ch * 2] =
                *(const uint32_t*)(srcs[a] + (size_t)r * D_ + ch * 2);
        }
        __syncthreads();
#pragma unroll
        for (int c = 0; c < 8; c++) {
            int ci = tid + c * 256;
            int d = ci >> 5, s2 = (ci & 31) * 2;
            uint32_t o = (uint32_t)__bfloat16_as_ushort(tile[s2][d]) |
                         ((uint32_t)__bfloat16_as_ushort(tile[s2 + 1][d]) << 16);
            *(uint32_t*)(dsts[a] + (size_t)d * S_ + s2) = o;
        }
    }
}

// ---------------------------------------------------------------------------
// Tensor-core causal flash attention. CTA = (q-tile 128, bh), 8 warps.
// K-tiles of 64; 3-buffer cp.async prefetch 2 ahead; ldmatrix fragments with
// hoisted loads + split-major MMA order; FMA-pipe exp2.
// ---------------------------------------------------------------------------
constexpr int ASTR = 72;
constexpr int AQ_E = 2 * 128 * ASTR;
constexpr int AKT_E = 64 * ASTR;
constexpr int AKSTAGE_E = 4 * AKT_E;
constexpr int ASMEM = (AQ_E + 3 * AKSTAGE_E) * 2;   // 147456 B

__global__ __launch_bounds__(256) void attn_mma() {
    extern __shared__ __nv_bfloat16 sma[];
    const uint32_t sma_u = smem_u32(sma);
    const int tid = threadIdx.x;
    const int lane = tid & 31;
    const int w = tid >> 5;
    const int g = lane >> 2, t = lane & 3;
    const int qt = (S_ / 128 - 1) - blockIdx.x;
    const int bh = blockIdx.y;
    const int nkt = 2 * qt + 2;

    __nv_bfloat16* QH = sma;
    __nv_bfloat16* QL = sma + 128 * ASTR;
    const uint32_t KV0_u = sma_u + AQ_E * 2;

    // ---- stage Q
    {
        const __nv_bfloat16* qsrc[2] = {
            g_qh + ((size_t)bh * S_ + qt * 128) * D_,
            g_ql + ((size_t)bh * S_ + qt * 128) * D_ };
#pragma unroll
        for (int c = 0; c < 8; c++) {
            int ci = tid + c * 256;
            int arr = ci >> 10;
            int idx = ci & 1023;
            int r = idx >> 3, ch = idx & 7;
            cp16(smem_u32(sma + arr * (128 * ASTR) + r * ASTR + ch * 8),
                 qsrc[arr] + (size_t)r * D_ + ch * 8);
        }
        CP_COMMIT();
    }

    auto issueKV = [&](int kt) {
        uint32_t st = KV0_u + (uint32_t)((kt % 3) * AKSTAGE_E) * 2;
        const __nv_bfloat16* bases[4] = {
            g_kh + ((size_t)bh * S_ + kt * 64) * D_,
            g_kl + ((size_t)bh * S_ + kt * 64) * D_,
            g_vth + (size_t)bh * D_ * S_ + kt * 64,
            g_vtl + (size_t)bh * D_ * S_ + kt * 64 };
#pragma unroll
        for (int c = 0; c < 8; c++) {
            int ci = tid + c * 256;
            int arr = ci >> 9;
            int idx = ci & 511;
            int r = idx >> 3, ch = idx & 7;
            const size_t rs = (arr < 2) ? (size_t)D_ : (size_t)S_;
            cp16(st + (uint32_t)(arr * AKT_E + r * ASTR + ch * 8) * 2,
                 bases[arr] + (size_t)r * rs + ch * 8);
        }
        CP_COMMIT();
    };

    issueKV(0);
    CP_WAIT1();
    __syncthreads();

    // ---- Q fragments (registers, whole CTA lifetime)
    uint32_t qfh[4][4], qfl[4][4];
#pragma unroll
    for (int ks = 0; ks < 4; ks++) {
        const int kb = ks * 16 + t * 2;
        const int r0 = (w * 16 + g) * ASTR;
        qfh[ks][0] = *(const uint32_t*)(QH + r0 + kb);
        qfh[ks][1] = *(const uint32_t*)(QH + r0 + 8 * ASTR + kb);
        qfh[ks][2] = *(const uint32_t*)(QH + r0 + kb + 8);
        qfh[ks][3] = *(const uint32_t*)(QH + r0 + 8 * ASTR + kb + 8);
        qfl[ks][0] = *(const uint32_t*)(QL + r0 + kb);
        qfl[ks][1] = *(const uint32_t*)(QL + r0 + 8 * ASTR + kb);
        qfl[ks][2] = *(const uint32_t*)(QL + r0 + kb + 8);
        qfl[ks][3] = *(const uint32_t*)(QL + r0 + 8 * ASTR + kb + 8);
    }

    issueKV(1);

    const uint32_t bfrag_off =
        (uint32_t)((((lane >> 4) & 1) * 8 + (lane & 7)) * ASTR +
                   ((lane >> 3) & 1) * 8) * 2;

    float o[8][4];
#pragma unroll
    for (int nt = 0; nt < 8; nt++)
#pragma unroll
        for (int e = 0; e < 4; e++) o[nt][e] = 0.f;
    float m0 = -1e30f, m1 = -1e30f, l0 = 0.f, l1 = 0.f;

    const int row0 = qt * 128 + w * 16 + g;
    const int row1 = row0 + 8;

    for (int kt = 0; kt < nkt; kt++) {
        if (kt + 1 < nkt) { CP_WAIT1(); } else { CP_WAIT0(); }
        __syncthreads();
        if (kt + 2 < nkt) issueKV(kt + 2);

        const uint32_t st = KV0_u + (uint32_t)((kt % 3) * AKSTAGE_E) * 2;
        const uint32_t uKH = st;
        const uint32_t uKL = st + AKT_E * 2;
        const uint32_t uVH = st + 2 * AKT_E * 2;
        const uint32_t uVL = st + 3 * AKT_E * 2;

        // ---- S = Q @ K^T (hoisted fragment loads, split-major order)
        float sc[8][4];
#pragma unroll
        for (int nt = 0; nt < 8; nt++)
#pragma unroll
            for (int e = 0; e < 4; e++) sc[nt][e] = 0.f;

#pragma unroll
        for (int ks = 0; ks < 4; ks++) {
            const uint32_t kso = (uint32_t)(ks * 16) * 2;
            uint32_t kh4[4][4], kl4[4][4];
#pragma unroll
            for (int ntp = 0; ntp < 4; ntp++) {
                const uint32_t ro = (uint32_t)(ntp * 16 * ASTR) * 2;
                ldsm_x4(kh4[ntp], uKH + bfrag_off + ro + kso);
                ldsm_x4(kl4[ntp], uKL + bfrag_off + ro + kso);
            }
#pragma unroll
            for (int ntp = 0; ntp < 4; ntp++) {
                mma16816(sc[2 * ntp],     qfh[ks], kh4[ntp][0], kh4[ntp][1]);
                mma16816(sc[2 * ntp + 1], qfh[ks], kh4[ntp][2], kh4[ntp][3]);
            }
#pragma unroll
            for (int ntp = 0; ntp < 4; ntp++) {
                mma16816(sc[2 * ntp],     qfl[ks], kh4[ntp][0], kh4[ntp][1]);
                mma16816(sc[2 * ntp + 1], qfl[ks], kh4[ntp][2], kh4[ntp][3]);
            }
#pragma unroll
            for (int ntp = 0; ntp < 4; ntp++) {
                mma16816(sc[2 * ntp],     qfh[ks], kl4[ntp][0], kl4[ntp][1]);
                mma16816(sc[2 * ntp + 1], qfh[ks], kl4[ntp][2], kl4[ntp][3]);
            }
        }

        // ---- causal mask
        if (kt >= 2 * qt) {
#pragma unroll
            for (int nt = 0; nt < 8; nt++) {
                const int c0 = kt * 64 + nt * 8 + 2 * t;
                if (c0 > row0)     sc[nt][0] = -1e30f;
                if (c0 + 1 > row0) sc[nt][1] = -1e30f;
                if (c0 > row1)     sc[nt][2] = -1e30f;
                if (c0 + 1 > row1) sc[nt][3] = -1e30f;
            }
        }

        // ---- online softmax (base-2, FMA pipe)
        float mx0 = -1e30f, mx1 = -1e30f;
#pragma unroll
        for (int nt = 0; nt < 8; nt++) {
            mx0 = fmaxf(mx0, fmaxf(sc[nt][0], sc[nt][1]));
            mx1 = fmaxf(mx1, fmaxf(sc[nt][2], sc[nt][3]));
        }
        mx0 = fmaxf(mx0, __shfl_xor_sync(0xffffffffu, mx0, 1));
        mx0 = fmaxf(mx0, __shfl_xor_sync(0xffffffffu, mx0, 2));
        mx1 = fmaxf(mx1, __shfl_xor_sync(0xffffffffu, mx1, 1));
        mx1 = fmaxf(mx1, __shfl_xor_sync(0xffffffffu, mx1, 2));

        const float mn0 = fmaxf(m0, mx0), mn1 = fmaxf(m1, mx1);
        const float a0 = exp2p(m0 - mn0), a1 = exp2p(m1 - mn1);
        m0 = mn0; m1 = mn1;

        float rs0 = 0.f, rs1 = 0.f;
#pragma unroll
        for (int nt = 0; nt < 8; nt++) {
            sc[nt][0] = exp2p(sc[nt][0] - mn0);
            sc[nt][1] = exp2p(sc[nt][1] - mn0);
            sc[nt][2] = exp2p(sc[nt][2] - mn1);
            sc[nt][3] = exp2p(sc[nt][3] - mn1);
            rs0 += sc[nt][0] + sc[nt][1];
            rs1 += sc[nt][2] + sc[nt][3];
        }
        rs0 += __shfl_xor_sync(0xffffffffu, rs0, 1);
        rs0 += __shfl_xor_sync(0xffffffffu, rs0, 2);
        rs1 += __shfl_xor_sync(0xffffffffu, rs1, 1);
        rs1 += __shfl_xor_sync(0xffffffffu, rs1, 2);
        l0 = l0 * a0 + rs0;
        l1 = l1 * a1 + rs1;

#pragma unroll
        for (int nt = 0; nt < 8; nt++) {
            o[nt][0] *= a0; o[nt][1] *= a0;
            o[nt][2] *= a1; o[nt][3] *= a1;
        }

        // ---- P fragments (FA layout) + hi/lo split
        uint32_t pfh[4][4], pfl[4][4];
#pragma unroll
        for (int ks = 0; ks < 4; ks++) {
            const float* p0 = sc[2 * ks];
            const float* p1 = sc[2 * ks + 1];
            pfh[ks][0] = pack_bf16x2(p0[0], p0[1]);
            pfh[ks][1] = pack_bf16x2(p0[2], p0[3]);
            pfh[ks][2] = pack_bf16x2(p1[0], p1[1]);
            pfh[ks][3] = pack_bf16x2(p1[2], p1[3]);
            pfl[ks][0] = pack_bf16x2(bf16_resid(p0[0]), bf16_resid(p0[1]));
            pfl[ks][1] = pack_bf16x2(bf16_resid(p0[2]), bf16_resid(p0[3]));
            pfl[ks][2] = pack_bf16x2(bf16_resid(p1[0]), bf16_resid(p1[1]));
            pfl[ks][3] = pack_bf16x2(bf16_resid(p1[2]), bf16_resid(p1[3]));
        }

        // ---- O += P @ V (hoisted loads, split-major order)
#pragma unroll
        for (int ks = 0; ks < 4; ks++) {
            const uint32_t kso = (uint32_t)(ks * 16) * 2;
            uint32_t vh4[4][4], vl4[4][4];
#pragma unroll
            for (int ntp = 0; ntp < 4; ntp++) {
                const uint32_t ro = (uint32_t)(ntp * 16 * ASTR) * 2;
                ldsm_x4(vh4[ntp], uVH + bfrag_off + ro + kso);
                ldsm_x4(vl4[ntp], uVL + bfrag_off + ro + kso);
            }
#pragma unroll
            for (int ntp = 0; ntp < 4; ntp++) {
                mma16816(o[2 * ntp],     pfh[ks], vh4[ntp][0], vh4[ntp][1]);
                mma16816(o[2 * ntp + 1], pfh[ks], vh4[ntp][2], vh4[ntp][3]);
            }
#pragma unroll
            for (int ntp = 0; ntp < 4; ntp++) {
                mma16816(o[2 * ntp],     pfl[ks], vh4[ntp][0], vh4[ntp][1]);
                mma16816(o[2 * ntp + 1], pfl[ks], vh4[ntp][2], vh4[ntp][3]);
            }
#pragma unroll
            for (int ntp = 0; ntp < 4; ntp++) {
                mma16816(o[2 * ntp],     pfh[ks], vl4[ntp][0], vl4[ntp][1]);
                mma16816(o[2 * ntp + 1], pfh[ks], vl4[ntp][2], vl4[ntp][3]);
            }
        }
    }

    // ---- epilogue: y = O / l, bf16 hi/lo, [b][s][h*64+d]
    const float inv0 = 1.0f / l0, inv1 = 1.0f / l1;
    const int b = bh >> 4, h = bh & 15;
#pragma unroll
    for (int nt = 0; nt < 8; nt++) {
        const int e = h * 64 + nt * 8 + 2 * t;
        {
            const size_t off = ((size_t)b * S_ + row0) * E_ + e;
            float v0 = o[nt][0] * inv0, v1 = o[nt][1] * inv0;
            *(uint32_t*)(g_yh + off) = pack_bf16x2(v0, v1);
            *(uint32_t*)(g_yl + off) =
                pack_bf16x2(bf16_resid(v0), bf16_resid(v1));
        }
        {
            const size_t off = ((size_t)b * S_ + row1) * E_ + e;
            float v0 = o[nt][2] * inv1, v1 = o[nt][3] * inv1;
            *(uint32_t*)(g_yh + off) = pack_bf16x2(v0, v1);
            *(uint32_t*)(g_yl + off) =
                pack_bf16x2(bf16_resid(v0), bf16_resid(v1));
        }
    }
}

// ---------------------------------------------------------------------------
// Launch
// ---------------------------------------------------------------------------
extern "C" void kernel_launch(void* const* d_in, const int* in_sizes, int n_in,
                              void* d_out, int out_size)
{
    const float* x      = (const float*)d_in[0];
    const float* W_kqv  = (const float*)d_in[1];
    const float* b_kqv  = (const float*)d_in[2];
    const float* W_proj = (const float*)d_in[3];
    const float* b_proj = (const float*)d_in[4];
    float* out = (float*)d_out;

    void *xh, *xl, *wkh, *wkl, *wph, *wpl, *yh, *yl;
    cudaGetSymbolAddress(&xh, g_xh);   cudaGetSymbolAddress(&xl, g_xl);
    cudaGetSymbolAddress(&wkh, g_wkh); cudaGetSymbolAddress(&wkl, g_wkl);
    cudaGetSymbolAddress(&wph, g_wph); cudaGetSymbolAddress(&wpl, g_wpl);
    cudaGetSymbolAddress(&yh, g_yh);   cudaGetSymbolAddress(&yl, g_yl);

    cudaFuncSetAttribute(gemm_cp<0>, cudaFuncAttributeMaxDynamicSharedMemorySize, GSMEM);
    cudaFuncSetAttribute(gemm_cp<1>, cudaFuncAttributeMaxDynamicSharedMemorySize, GSMEM);
    cudaFuncSetAttribute(attn_mma,   cudaFuncAttributeMaxDynamicSharedMemorySize, ASMEM);

    // 0) split inputs to bf16 hi/lo
    {
        int n4 = M_ * E_ / 4;
        split_kernel<<<(n4 + 255) / 256, 256>>>(
            x, (__nv_bfloat16*)xh, (__nv_bfloat16*)xl, n4);
        n4 = NKQV * E_ / 4;
        split_kernel<<<(n4 + 255) / 256, 256>>>(
            W_kqv, (__nv_bfloat16*)wkh, (__nv_bfloat16*)wkl, n4);
        n4 = E_ * E_ / 4;
        split_kernel<<<(n4 + 255) / 256, 256>>>(
            W_proj, (__nv_bfloat16*)wph, (__nv_bfloat16*)wpl, n4);
    }

    // 1) QKV projection -> q/k/v bf16 hi/lo (q pre-scaled)
    gemm_cp<1><<<dim3(NKQV / 128, M_ / 128), 256, GSMEM>>>(
        (const __nv_bfloat16*)xh, (const __nv_bfloat16*)xl,
        (const __nv_bfloat16*)wkh, (const __nv_bfloat16*)wkl,
        b_kqv, nullptr, M_, NKQV, E_);

    // 2) V transpose [bh][s][d] -> [bh][d][s]
    vtrans_kernel<<<dim3(S_ / 64, B_ * H_), 256>>>();

    // 3) Tensor-core causal flash attention -> y bf16 hi/lo
    attn_mma<<<dim3(S_ / 128, B_ * H_), 256, ASMEM>>>();

    // 4) Output projection -> d_out (fp32)
    gemm_cp<0><<<dim3(E_ / 128, M_ / 128), 256, GSMEM>>>(
        (const __nv_bfloat16*)yh, (const __nv_bfloat16*)yl,
        (const __nv_bfloat16*)wph, (const __nv_bfloat16*)wpl,
        b_proj, out, M_, E_, E_);
}